// round 15
// baseline (speedup 1.0000x reference)
#include <cuda_runtime.h>
#include <cuda_bf16.h>
#include <math.h>
#include <stdint.h>

#define NB   16
#define D    256
#define NH   8
#define NTOK 98
#define NWIN 512
#define SEH  64
#define H1   56
#define H2   28
#define H3   14
#define MROWS 50176

typedef unsigned long long ull;

// ---------------- scratch ----------------
__device__ __align__(16) __nv_bfloat16 g_Yh[(size_t)NB*H1*H1*D];
__device__ __align__(16) __nv_bfloat16 g_Yl[(size_t)NB*H1*H1*D];
__device__ __align__(16) float g_z  [(size_t)NB*H1*H1*D];
__device__ __align__(16) float g_xg1[NB*H2*H2*D];
__device__ __align__(16) float g_xg2[NB*H3*H3*D];
__device__ __align__(16) float g_part[NB*64*D];
__device__ __align__(16) float g_svec [NB*D];
__device__ __align__(16) float g_gout [8*4*NTOK*D];
__device__ __align__(16) float g_qglob[8*NTOK*D];
__device__ __align__(16) float g_kv   [(size_t)MROWS*2*D];
__device__ __align__(16) float g_biasb[NH*NTOK*NTOK];
__device__ __align__(16) float g_S    [32*NTOK*NTOK];
__device__ __align__(16) __nv_bfloat16 g_aouth[(size_t)MROWS*256], g_aoutl[(size_t)MROWS*256];
__device__ __align__(16) __nv_bfloat16 g_Wqh[512*256], g_Wql[512*256];
__device__ __align__(16) __nv_bfloat16 g_Woh[256*256], g_Wol[256*256];
__device__ __align__(16) __nv_bfloat16 g_Bph[NB*256*256], g_Bpl[NB*256*256];

// fast tanh-form GELU (NaN-safe); inputs here are small (|x|<~1) where
// the tanh approximation error is O(x^5) << 1e-6
__device__ __forceinline__ float gelu_f(float v){
    float u=v*(0.7978845608028654f + 0.035677408136300125f*v*v);
    float e=__expf(2.f*u);
    float t=1.f-2.f/(e+1.f);
    return 0.5f*v*(1.f+t);
}
__device__ __forceinline__ long xrow_off(int r){
    int win=r/NTOK, i=r%NTOK;
    int b=win>>6, gx=(win>>3)&7, gy=win&7;
    int m=i/49, rr=i%49, w1=rr/7, w2=rr%7;
    return (((((long)(b*2+m)*8+gx)*8+gy)*7+w1)*7+w2)*256;
}
__device__ __forceinline__ long pix_off(int n, int hp, int wp){
    int gx=hp/7, w1=hp-gx*7, gy=wp/7, w2=wp-gy*7;
    return (((((long)n*8+gx)*8+gy)*7+w1)*7+w2)*256;
}
__device__ __forceinline__ ull pk2(float a){ ull r; asm("mov.b64 %0,{%1,%1};":"=l"(r):"f"(a)); return r; }
__device__ __forceinline__ void fma2(ull&d, ull a, ull b){ asm("fma.rn.f32x2 %0,%1,%2,%0;":"+l"(d):"l"(a),"l"(b)); }
__device__ __forceinline__ float2 upk(ull v){ float2 r; asm("mov.b64 {%0,%1},%2;":"=f"(r.x),"=f"(r.y):"l"(v)); return r; }

__device__ __forceinline__ uint32_t smem_u32(const void* p){
    uint32_t a;
    asm("{ .reg .u64 t; cvta.to.shared.u64 t, %1; cvt.u32.u64 %0, t; }":"=r"(a):"l"(p));
    return a;
}
__device__ __forceinline__ void ldsm4(uint32_t* r, uint32_t a){
    asm volatile("ldmatrix.sync.aligned.m8n8.x4.shared.b16 {%0,%1,%2,%3},[%4];"
        :"=r"(r[0]),"=r"(r[1]),"=r"(r[2]),"=r"(r[3]):"r"(a));
}
__device__ __forceinline__ void ldsm2(uint32_t* r, uint32_t a){
    asm volatile("ldmatrix.sync.aligned.m8n8.x2.shared.b16 {%0,%1},[%2];"
        :"=r"(r[0]),"=r"(r[1]):"r"(a));
}
__device__ __forceinline__ void mma16816(float* d, const uint32_t* a, const uint32_t* b){
    asm volatile("mma.sync.aligned.m16n8k16.row.col.f32.bf16.bf16.f32 "
        "{%0,%1,%2,%3},{%4,%5,%6,%7},{%8,%9},{%0,%1,%2,%3};"
        : "+f"(d[0]),"+f"(d[1]),"+f"(d[2]),"+f"(d[3])
        : "r"(a[0]),"r"(a[1]),"r"(a[2]),"r"(a[3]),"r"(b[0]),"r"(b[1]));
}
__device__ __forceinline__ uint32_t bsplit2(float a, float b, uint32_t& lo){
    __nv_bfloat16 ha=__float2bfloat16(a), hb=__float2bfloat16(b);
    __nv_bfloat16 la=__float2bfloat16(a-__bfloat162float(ha));
    __nv_bfloat16 lb=__float2bfloat16(b-__bfloat162float(hb));
    __nv_bfloat162 h2; h2.x=ha; h2.y=hb;
    __nv_bfloat162 l2; l2.x=la; l2.y=lb;
    lo=*(uint32_t*)&l2;
    return *(uint32_t*)&h2;
}

extern __shared__ float dsm[];

// ---------------- weight transpose + hi/lo split ----------------
__global__ void k_prep_w(const float* __restrict__ W, __nv_bfloat16* __restrict__ Wh,
                         __nv_bfloat16* __restrict__ Wl, int N){
    int o=blockIdx.x*blockDim.x+threadIdx.x;
    if(o>=N*256) return;
    int n=o>>8, k=o&255;
    float v=W[k*N+n];
    __nv_bfloat16 h=__float2bfloat16(v);
    Wh[o]=h;
    Wl[o]=__float2bfloat16(v-__bfloat162float(h));
}

// ---------------- prestore pw*sv bf16 hi/lo per image ----------------
__global__ void k_prep_pwsv(const float* __restrict__ pw, const float* __restrict__ svg,
        __nv_bfloat16* __restrict__ Bh, __nv_bfloat16* __restrict__ Bl){
    int n=blockIdx.y;
    int o=(blockIdx.x*256+threadIdx.x)*4;   // element index into 256*256
    if(o>=256*256) return;
    int ci=o&255;
    float4 v=*(const float4*)&pw[o];
    float4 s=*(const float4*)&svg[n*256+ci];
    float vv[4]={v.x*s.x,v.y*s.y,v.z*s.z,v.w*s.w};
    __nv_bfloat16 h[4], l[4];
    #pragma unroll
    for(int u=0;u<4;u++){
        h[u]=__float2bfloat16(vv[u]);
        l[u]=__float2bfloat16(vv[u]-__bfloat162float(h[u]));
    }
    long ob=(long)n*65536+o;
    *(ull*)&Bh[ob]=*(ull*)h;
    *(ull*)&Bl[ob]=*(ull*)l;
}

// ---------------- NHWC depthwise 3x3 + gelu, 4 pixels x 4 channels / thread ----------------
__global__ void __launch_bounds__(256) k_dwconv_nhwc(const float* __restrict__ in,
        const float* __restrict__ dw, __nv_bfloat16* __restrict__ Yh,
        __nv_bfloat16* __restrict__ Yl, int HW, int windowed){
    int gid=blockIdx.x*256+threadIdx.x;
    int W4=HW>>2;
    int cq=gid&63; int t=gid>>6;
    int wq=t%W4; t/=W4;
    int hy=t%HW; int n=t/HW;
    if(n>=NB) return;
    int c=cq*4, wx0=wq*4;
    long base = windowed ? (long)n*(64*49*256) : (long)n*HW*HW*256;
    int coff[6];
    #pragma unroll
    for(int u=0;u<6;u++){
        int ww=wx0-1+u;
        if(ww<0||ww>=HW){ coff[u]=-1; }
        else if(windowed){ int gy=ww/7, w2=ww-gy*7; coff[u]=gy*(49*256)+w2*256; }
        else coff[u]=ww*256;
    }
    float acc[4][4]={};
    #pragma unroll
    for(int kh=0;kh<3;kh++){
        int hh=hy+kh-1;
        if(hh<0||hh>=HW) continue;
        long ro;
        if(windowed){ int gx=hh/7, w1=hh-gx*7; ro=base + gx*(8*49*256) + w1*(7*256); }
        else ro=base + (long)hh*HW*256;
        float4 r[6];
        #pragma unroll
        for(int u=0;u<6;u++)
            r[u]=(coff[u]>=0)? *(const float4*)&in[ro+coff[u]+c] : make_float4(0.f,0.f,0.f,0.f);
        float wv[3][4];
        #pragma unroll
        for(int kw=0;kw<3;kw++)
            #pragma unroll
            for(int u=0;u<4;u++) wv[kw][u]=__ldg(&dw[(c+u)*9+kh*3+kw]);
        #pragma unroll
        for(int kw=0;kw<3;kw++){
            #pragma unroll
            for(int px=0;px<4;px++){
                float4 v=r[px+kw];
                acc[px][0]+=v.x*wv[kw][0];
                acc[px][1]+=v.y*wv[kw][1];
                acc[px][2]+=v.z*wv[kw][2];
                acc[px][3]+=v.w*wv[kw][3];
            }
        }
    }
    #pragma unroll
    for(int px=0;px<4;px++){
        __nv_bfloat16 h[4], l[4];
        #pragma unroll
        for(int u=0;u<4;u++){
            float g=gelu_f(acc[px][u]);
            h[u]=__float2bfloat16(g);
            l[u]=__float2bfloat16(g-__bfloat162float(h[u]));
        }
        long ob=((long)n*HW*HW + hy*HW + wx0+px)*256 + c;
        *(ull*)&Yh[ob]=*(ull*)h;
        *(ull*)&Yl[ob]=*(ull*)l;
    }
}

// ---------------- SE stage 1 ----------------
__global__ void k_semean(const __nv_bfloat16* __restrict__ Yh,
        const __nv_bfloat16* __restrict__ Yl, int P, int nch){
    int blk=blockIdx.x;
    int n=blk/nch, ch=blk%nch;
    int t=threadIdx.x;
    int cnt=P/nch;
    const __nv_bfloat16* ph=Yh+((long)n*P + (long)ch*cnt)*256 + t;
    const __nv_bfloat16* pl=Yl+((long)n*P + (long)ch*cnt)*256 + t;
    float s=0.f;
    for(int p=0;p<cnt;p++){
        s += __bfloat162float(ph[(long)p*256]) + __bfloat162float(pl[(long)p*256]);
    }
    g_part[((long)n*64+ch)*256 + t]=s;
}

// ---------------- SE stage 2 ----------------
__global__ void k_se2(const float* __restrict__ se1, const float* __restrict__ se2,
                      float* __restrict__ sv, int P, int nch){
    int n=blockIdx.x;
    __shared__ float sin_[D];
    __shared__ float hid[SEH];
    int t=threadIdx.x;
    float s=0.f;
    for(int j=0;j<nch;j++) s+=g_part[((long)n*64+j)*256 + t];
    sin_[t]=s/(float)P;
    __syncthreads();
    if(t<SEH){
        float a=0.f;
        for(int c=0;c<D;c++) a+=sin_[c]*se1[c*SEH+t];
        hid[t]=gelu_f(a);
    }
    __syncthreads();
    float a=0.f;
    for(int j=0;j<SEH;j++) a+=hid[j]*se2[j*D+t];
    sv[n*D+t]=1.f/(1.f+expf(-a));
}

// ---------------- HMMA pointwise conv (B prestored bf16) ----------------
#define SSTR 40
__global__ void __launch_bounds__(256) k_pwmma(const __nv_bfloat16* __restrict__ Yh,
        const __nv_bfloat16* __restrict__ Yl, float* __restrict__ z, int P){
    __shared__ __align__(16) __nv_bfloat16 sAh[128*SSTR];
    __shared__ __align__(16) __nv_bfloat16 sAl[128*SSTR];
    __shared__ __align__(16) __nv_bfloat16 sBh[128*SSTR];
    __shared__ __align__(16) __nv_bfloat16 sBl[128*SSTR];
    int tid=threadIdx.x;
    int wid=tid>>5, lane=tid&31;
    int wm=wid&1, wn=wid>>1;
    int n=blockIdx.z;
    int m0=blockIdx.y*128, n0=blockIdx.x*128;
    const __nv_bfloat16* Yhb=Yh+(long)n*P*256;
    const __nv_bfloat16* Ylb=Yl+(long)n*P*256;
    const __nv_bfloat16* Bph=g_Bph+(long)n*65536;
    const __nv_bfloat16* Bpl=g_Bpl+(long)n*65536;
    float* zb=z+(long)n*P*256;

    uint32_t bAh=smem_u32(sAh), bAl=smem_u32(sAl);
    uint32_t bBh=smem_u32(sBh), bBl=smem_u32(sBl);

    float acc[4][4][4];
    #pragma unroll
    for(int i=0;i<4;i++)
        #pragma unroll
        for(int j=0;j<4;j++)
            #pragma unroll
            for(int e=0;e<4;e++) acc[i][j][e]=0.f;

    int arow=lane&15,  acol=(lane>>4)*8;
    int brow=lane&7,   bcol=((lane>>3)&1)*8;
    int lrow=tid>>1, lcb=(tid&1)*16;
    int pr=m0+lrow; if(pr>=P) pr=P-1;

    for(int c=0;c<8;c++){
        int k0=c*32;
        {
            int sb=lrow*SSTR+lcb;
            const __nv_bfloat16* sh=&Yhb[(long)pr*256+k0+lcb];
            const __nv_bfloat16* sl=&Ylb[(long)pr*256+k0+lcb];
            *(uint4*)&sAh[sb]  =*(const uint4*)&sh[0];
            *(uint4*)&sAh[sb+8]=*(const uint4*)&sh[8];
            *(uint4*)&sAl[sb]  =*(const uint4*)&sl[0];
            *(uint4*)&sAl[sb+8]=*(const uint4*)&sl[8];
        }
        {
            long bo=(long)(n0+lrow)*256+k0+lcb;
            int sb=lrow*SSTR+lcb;
            *(uint4*)&sBh[sb]  =*(const uint4*)&Bph[bo];
            *(uint4*)&sBh[sb+8]=*(const uint4*)&Bph[bo+8];
            *(uint4*)&sBl[sb]  =*(const uint4*)&Bpl[bo];
            *(uint4*)&sBl[sb+8]=*(const uint4*)&Bpl[bo+8];
        }
        __syncthreads();
        #pragma unroll
        for(int ks=0;ks<2;ks++){
            int kk=ks*16;
            uint32_t bh[4][2], bl[4][2];
            #pragma unroll
            for(int nt=0;nt<4;nt++){
                uint32_t boff=(uint32_t)((wn*32+nt*8+brow)*SSTR + kk+bcol)*2u;
                ldsm2(bh[nt], bBh+boff);
                ldsm2(bl[nt], bBl+boff);
            }
            #pragma unroll
            for(int mt=0;mt<4;mt++){
                uint32_t aoff=(uint32_t)((wm*64+mt*16+arow)*SSTR + kk+acol)*2u;
                uint32_t ah[4], al[4];
                ldsm4(ah, bAh+aoff);
                ldsm4(al, bAl+aoff);
                #pragma unroll
                for(int nt=0;nt<4;nt++){
                    mma16816(acc[mt][nt], ah, bh[nt]);
                    mma16816(acc[mt][nt], al, bh[nt]);
                    mma16816(acc[mt][nt], ah, bl[nt]);
                }
            }
        }
        __syncthreads();
    }

    int rl=lane>>2, cl=(lane&3)*2;
    #pragma unroll
    for(int mt=0;mt<4;mt++){
        int r0=wm*64+mt*16+rl, r1=r0+8;
        #pragma unroll
        for(int nt=0;nt<4;nt++){
            int nl=wn*32+nt*8+cl;
            float* d=acc[mt][nt];
            if(m0+r0<P) *(float2*)&zb[(long)(m0+r0)*256 + n0+nl]=make_float2(d[0],d[1]);
            if(m0+r1<P) *(float2*)&zb[(long)(m0+r1)*256 + n0+nl]=make_float2(d[2],d[3]);
        }
    }
}

// ---------------- NHWC residual + maxpool ----------------
__global__ void k_respool_nhwc(const float* __restrict__ xin, const float* __restrict__ z,
        float* __restrict__ out, int Hin, int Hout, int windowed){
    int gid=blockIdx.x*256+threadIdx.x;
    int cq=gid&63; int t=gid>>6;
    int wo=t%Hout; t/=Hout;
    int ho=t%Hout; int n=t/Hout;
    if(n>=NB) return;
    int c=cq*4;
    float4 mx=make_float4(-INFINITY,-INFINITY,-INFINITY,-INFINITY);
    #pragma unroll
    for(int kh=0;kh<3;kh++){
        int hh=2*ho-1+kh;
        if(hh<0||hh>=Hin) continue;
        #pragma unroll
        for(int kw=0;kw<3;kw++){
            int ww=2*wo-1+kw;
            if(ww<0||ww>=Hin) continue;
            long zoff=((long)n*Hin*Hin + hh*Hin+ww)*256 + c;
            float4 a=*(const float4*)&z[zoff];
            long xoff = windowed ? pix_off(n,hh,ww)+c : zoff;
            float4 b=*(const float4*)&xin[xoff];
            mx.x=fmaxf(mx.x,a.x+b.x); mx.y=fmaxf(mx.y,a.y+b.y);
            mx.z=fmaxf(mx.z,a.z+b.z); mx.w=fmaxf(mx.w,a.w+b.w);
        }
    }
    *(float4*)&out[((long)n*Hout*Hout + ho*Hout+wo)*256 + c]=mx;
}

// ---------------- HMMA GEMM (QKV mode0 / to_out mode1) ----------------
__global__ void __launch_bounds__(256) k_mmagemm(const float* __restrict__ Axf,
        const __nv_bfloat16* __restrict__ Ah_, const __nv_bfloat16* __restrict__ Al_,
        const __nv_bfloat16* __restrict__ Wh, const __nv_bfloat16* __restrict__ Wl,
        const float* __restrict__ bias, float* __restrict__ Cb, int mode){
    __shared__ __align__(16) __nv_bfloat16 sAh[128*SSTR];
    __shared__ __align__(16) __nv_bfloat16 sAl[128*SSTR];
    __shared__ __align__(16) __nv_bfloat16 sBh[128*SSTR];
    __shared__ __align__(16) __nv_bfloat16 sBl[128*SSTR];
    __shared__ long roff[128];
    __shared__ float bsh[128];

    int tid=threadIdx.x;
    int wid=tid>>5, lane=tid&31;
    int wm=wid&1, wn=wid>>1;
    int m0=blockIdx.y*128, n0=blockIdx.x*128;

    if(tid<128){
        roff[tid]=xrow_off(m0+tid);
        if(mode==0) bsh[tid]=bias[n0+tid];
    }
    __syncthreads();

    uint32_t bAh=smem_u32(sAh), bAl=smem_u32(sAl);
    uint32_t bBh=smem_u32(sBh), bBl=smem_u32(sBl);

    float acc[4][4][4];
    #pragma unroll
    for(int i=0;i<4;i++)
        #pragma unroll
        for(int j=0;j<4;j++)
            #pragma unroll
            for(int e=0;e<4;e++) acc[i][j][e]=0.f;

    int arow=lane&15,  acol=(lane>>4)*8;
    int brow=lane&7,   bcol=((lane>>3)&1)*8;
    int lrow=tid>>1, lcb=(tid&1)*16;

    for(int c=0;c<8;c++){
        int k0=c*32;
        if(mode==0){
            const float* src=&Axf[roff[lrow]+k0+lcb];
            __nv_bfloat16 h[16], l[16];
            #pragma unroll
            for(int g=0;g<4;g++){
                float4 v=*(const float4*)&src[g*4];
                float vv[4]={v.x,v.y,v.z,v.w};
                #pragma unroll
                for(int u=0;u<4;u++){
                    __nv_bfloat16 hh=__float2bfloat16(vv[u]);
                    h[g*4+u]=hh;
                    l[g*4+u]=__float2bfloat16(vv[u]-__bfloat162float(hh));
                }
            }
            int sb=lrow*SSTR+lcb;
            *(uint4*)&sAh[sb]  =*(const uint4*)&h[0];
            *(uint4*)&sAh[sb+8]=*(const uint4*)&h[8];
            *(uint4*)&sAl[sb]  =*(const uint4*)&l[0];
            *(uint4*)&sAl[sb+8]=*(const uint4*)&l[8];
        }else{
            int sb=lrow*SSTR+lcb;
            const __nv_bfloat16* sh=&Ah_[(long)(m0+lrow)*256+k0+lcb];
            const __nv_bfloat16* sl=&Al_[(long)(m0+lrow)*256+k0+lcb];
            *(uint4*)&sAh[sb]  =*(const uint4*)&sh[0];
            *(uint4*)&sAh[sb+8]=*(const uint4*)&sh[8];
            *(uint4*)&sAl[sb]  =*(const uint4*)&sl[0];
            *(uint4*)&sAl[sb+8]=*(const uint4*)&sl[8];
        }
        {
            const __nv_bfloat16* sh=&Wh[(long)(n0+lrow)*256+k0+lcb];
            const __nv_bfloat16* sl=&Wl[(long)(n0+lrow)*256+k0+lcb];
            int sb=lrow*SSTR+lcb;
            *(uint4*)&sBh[sb]  =*(const uint4*)&sh[0];
            *(uint4*)&sBh[sb+8]=*(const uint4*)&sh[8];
            *(uint4*)&sBl[sb]  =*(const uint4*)&sl[0];
            *(uint4*)&sBl[sb+8]=*(const uint4*)&sl[8];
        }
        __syncthreads();
        #pragma unroll
        for(int ks=0;ks<2;ks++){
            int kk=ks*16;
            uint32_t bh[4][2], bl[4][2];
            #pragma unroll
            for(int nt=0;nt<4;nt++){
                uint32_t boff=(uint32_t)((wn*32+nt*8+brow)*SSTR + kk+bcol)*2u;
                ldsm2(bh[nt], bBh+boff);
                ldsm2(bl[nt], bBl+boff);
            }
            #pragma unroll
            for(int mt=0;mt<4;mt++){
                uint32_t aoff=(uint32_t)((wm*64+mt*16+arow)*SSTR + kk+acol)*2u;
                uint32_t ah[4], al[4];
                ldsm4(ah, bAh+aoff);
                ldsm4(al, bAl+aoff);
                #pragma unroll
                for(int nt=0;nt<4;nt++){
                    mma16816(acc[mt][nt], ah, bh[nt]);
                    mma16816(acc[mt][nt], al, bh[nt]);
                    mma16816(acc[mt][nt], ah, bl[nt]);
                }
            }
        }
        __syncthreads();
    }

    int rl=lane>>2, cl=(lane&3)*2;
    #pragma unroll
    for(int mt=0;mt<4;mt++){
        int r0=wm*64+mt*16+rl, r1=r0+8;
        #pragma unroll
        for(int nt=0;nt<4;nt++){
            int nl=wn*32+nt*8+cl;
            float* d=acc[mt][nt];
            if(mode==0){
                float b0=bsh[nl], b1=bsh[nl+1];
                float* p0=&g_kv[(long)(m0+r0)*512 + n0+nl];
                float* p1=&g_kv[(long)(m0+r1)*512 + n0+nl];
                p0[0]=d[0]+b0; p0[1]=d[1]+b1;
                p1[0]=d[2]+b0; p1[1]=d[3]+b1;
            }else{
                float* p0=&Cb[roff[r0] + n0+nl];
                float* p1=&Cb[roff[r1] + n0+nl];
                p0[0]=d[0]; p0[1]=d[1];
                p1[0]=d[2]; p1[1]=d[3];
            }
        }
    }
}

// ---------------- HMMA window attention (register-resident P) ----------------
#define QSTR 40
#define PSTR 120
#define OQH 0
#define OQL (OQH+112*QSTR)
#define OKH (OQL+112*QSTR)
#define OKL (OKH+112*QSTR)
#define OVH (OKL+112*QSTR)
#define OVL (OVH+32*PSTR)
#define WSM_HALVES (OVL+32*PSTR)
__global__ void __launch_bounds__(256,2) k_wattn(){
    __nv_bfloat16* sb=(__nv_bfloat16*)dsm;
    int wh=blockIdx.x; int head=wh&7; int win=wh>>3; int b=win>>6;
    int tid=threadIdx.x, wid=tid>>5, lane=tid&31;
    const float scale=0.17677669529663687f;

    for(int e=tid;e<WSM_HALVES/8;e+=256) ((uint4*)sb)[e]=make_uint4(0,0,0,0);
    __syncthreads();

    for(int e=tid;e<224;e+=256){
        int row=e>>1, half=(e&1)*16;
        if(row<98){
            const float* qs=&g_qglob[((long)b*98+row)*256 + head*32 + half];
            const float* ks=&g_kv[(((long)win*98+row))*512 + head*32 + half];
            uint32_t qh[8], ql[8], kh[8], kl[8];
            #pragma unroll
            for(int u=0;u<8;u++){
                float q0=qs[2*u]*scale, q1=qs[2*u+1]*scale;
                qh[u]=bsplit2(q0,q1,ql[u]);
                kh[u]=bsplit2(ks[2*u],ks[2*u+1],kl[u]);
            }
            int sbo=row*QSTR+half;
            *(uint4*)&sb[OQH+sbo]  =*(uint4*)&qh[0];
            *(uint4*)&sb[OQH+sbo+8]=*(uint4*)&qh[4];
            *(uint4*)&sb[OQL+sbo]  =*(uint4*)&ql[0];
            *(uint4*)&sb[OQL+sbo+8]=*(uint4*)&ql[4];
            *(uint4*)&sb[OKH+sbo]  =*(uint4*)&kh[0];
            *(uint4*)&sb[OKH+sbo+8]=*(uint4*)&kh[4];
            *(uint4*)&sb[OKL+sbo]  =*(uint4*)&kl[0];
            *(uint4*)&sb[OKL+sbo+8]=*(uint4*)&kl[4];
        }
    }
    for(int e=tid;e<196;e+=256){
        int row=e>>1, half=(e&1)*16;
        const float* vs=&g_kv[(((long)win*98+row))*512 + 256 + head*32 + half];
        #pragma unroll
        for(int u=0;u<16;u++){
            float vv=vs[u];
            __nv_bfloat16 h=__float2bfloat16(vv);
            __nv_bfloat16 l=__float2bfloat16(vv-__bfloat162float(h));
            int c=half+u;
            sb[OVH+c*PSTR+row]=h;
            sb[OVL+c*PSTR+row]=l;
        }
    }
    __syncthreads();

    uint32_t base=smem_u32(sb);
    int arow=lane&15, acol=(lane>>4)*8;
    int brow=lane&7,  bcol=((lane>>3)&1)*8;
    int rl=lane>>2, cl=(lane&3)*2;

    if(wid<7){
        float sacc[13][4];
        #pragma unroll
        for(int nt=0;nt<13;nt++){
            #pragma unroll
            for(int e2=0;e2<4;e2++) sacc[nt][e2]=0.f;
        }
        #pragma unroll
        for(int kc=0;kc<2;kc++){
            int kk=kc*16;
            uint32_t aoff=(uint32_t)((wid*16+arow)*QSTR + kk+acol)*2u;
            uint32_t ah[4], al[4];
            ldsm4(ah, base+(OQH*2u)+aoff);
            ldsm4(al, base+(OQL*2u)+aoff);
            #pragma unroll
            for(int nt=0;nt<13;nt++){
                uint32_t boff=(uint32_t)((nt*8+brow)*QSTR + kk+bcol)*2u;
                uint32_t bh[2], bl[2];
                ldsm2(bh, base+(OKH*2u)+boff);
                ldsm2(bl, base+(OKL*2u)+boff);
                mma16816(sacc[nt], ah, bh);
                mma16816(sacc[nt], al, bh);
                mma16816(sacc[nt], ah, bl);
            }
        }
        int r0=wid*16+rl, r1=r0+8;
        const float* bbase=&g_biasb[(long)head*9604];
        #pragma unroll
        for(int nt=0;nt<13;nt++){
            int j0=nt*8+cl;
            if(j0>=98){
                sacc[nt][0]=-1e30f; sacc[nt][1]=-1e30f;
                sacc[nt][2]=-1e30f; sacc[nt][3]=-1e30f;
            }else{
                if(r0<98){
                    float2 bb=*(const float2*)&bbase[r0*98+j0];
                    sacc[nt][0]+=bb.x; sacc[nt][1]+=bb.y;
                }
                if(r1<98){
                    float2 bb=*(const float2*)&bbase[r1*98+j0];
                    sacc[nt][2]+=bb.x; sacc[nt][3]+=bb.y;
                }
            }
        }
        float mx0=-1e30f, mx1=-1e30f;
        #pragma unroll
        for(int nt=0;nt<13;nt++){
            mx0=fmaxf(mx0,fmaxf(sacc[nt][0],sacc[nt][1]));
            mx1=fmaxf(mx1,fmaxf(sacc[nt][2],sacc[nt][3]));
        }
        mx0=fmaxf(mx0,__shfl_xor_sync(~0u,mx0,1)); mx0=fmaxf(mx0,__shfl_xor_sync(~0u,mx0,2));
        mx1=fmaxf(mx1,__shfl_xor_sync(~0u,mx1,1)); mx1=fmaxf(mx1,__shfl_xor_sync(~0u,mx1,2));
        float sum0=0.f, sum1=0.f;
        #pragma unroll
        for(int nt=0;nt<13;nt++){
            sacc[nt][0]=__expf(sacc[nt][0]-mx0); sum0+=sacc[nt][0];
            sacc[nt][1]=__expf(sacc[nt][1]-mx0); sum0+=sacc[nt][1];
            sacc[nt][2]=__expf(sacc[nt][2]-mx1); sum1+=sacc[nt][2];
            sacc[nt][3]=__expf(sacc[nt][3]-mx1); sum1+=sacc[nt][3];
        }
        sum0+=__shfl_xor_sync(~0u,sum0,1); sum0+=__shfl_xor_sync(~0u,sum0,2);
        sum1+=__shfl_xor_sync(~0u,sum1,1); sum1+=__shfl_xor_sync(~0u,sum1,2);
        float inv0=1.f/sum0, inv1=1.f/sum1;

        uint32_t phi[7][4], plo[7][4];
        #pragma unroll
        for(int t7=0;t7<7;t7++){
            int nt0=2*t7, nt1=2*t7+1;
            phi[t7][0]=bsplit2(sacc[nt0][0]*inv0, sacc[nt0][1]*inv0, plo[t7][0]);
            phi[t7][1]=bsplit2(sacc[nt0][2]*inv1, sacc[nt0][3]*inv1, plo[t7][1]);
            if(nt1<13){
                phi[t7][2]=bsplit2(sacc[nt1][0]*inv0, sacc[nt1][1]*inv0, plo[t7][2]);
                phi[t7][3]=bsplit2(sacc[nt1][2]*inv1, sacc[nt1][3]*inv1, plo[t7][3]);
            }else{
                phi[t7][2]=0u; plo[t7][2]=0u;
                phi[t7][3]=0u; plo[t7][3]=0u;
            }
        }

        float oacc[4][4];
        #pragma unroll
        for(int nt=0;nt<4;nt++)
            #pragma unroll
            for(int e2=0;e2<4;e2++) oacc[nt][e2]=0.f;
        #pragma unroll
        for(int t7=0;t7<7;t7++){
            int kk=t7*16;
            #pragma unroll
            for(int nt=0;nt<4;nt++){
                uint32_t boff=(uint32_t)((nt*8+brow)*PSTR + kk+bcol)*2u;
                uint32_t bh[2], bl[2];
                ldsm2(bh, base+(OVH*2u)+boff);
                ldsm2(bl, base+(OVL*2u)+boff);
                mma16816(oacc[nt], phi[t7], bh);
                mma16816(oacc[nt], plo[t7], bh);
                mma16816(oacc[nt], phi[t7], bl);
            }
        }
        #pragma unroll
        for(int nt=0;nt<4;nt++){
            int c=nt*8+cl;
            uint32_t lo0, lo1;
            uint32_t hi0=bsplit2(oacc[nt][0], oacc[nt][1], lo0);
            uint32_t hi1=bsplit2(oacc[nt][2], oacc[nt][3], lo1);
            if(r0<98){
                long bse=((long)win*98+r0)*256 + head*32 + c;
                *(uint32_t*)&g_aouth[bse]=hi0;
                *(uint32_t*)&g_aoutl[bse]=lo0;
            }
            if(r1<98){
                long bse=((long)win*98+r1)*256 + head*32 + c;
                *(uint32_t*)&g_aouth[bse]=hi1;
                *(uint32_t*)&g_aoutl[bse]=lo1;
            }
        }
    }
}

// ---------------- gattn stage 1 ----------------
__global__ void k_gattn1(){
    float* X=dsm;
    float* S=dsm+98*260;
    int bg=blockIdx.x, chunk=blockIdx.y;
    int b=bg>>2, g=bg&3, nx=g>>1, ny=g&1;
    int tid=threadIdx.x;
    for(int e=tid;e<98*256;e+=256){
        int c=e&255, i=e>>8;
        int m=i/49, rr=i%49, w1=rr/7, w2=rr%7;
        int n=b*2+m;
        int pix=(nx*7+w1)*14 + ny*7+w2;
        X[i*260+c]=g_xg2[((long)n*196+pix)*256 + c];
    }
    __syncthreads();
    int i0=chunk*26;
    int ni=min(26,98-i0);
    int npair=ni>>1;
    for(int t=tid;t<13*49;t+=256){
        int ip=t/49, jp=t%49;
        if(ip>=npair) continue;
        int i=i0+ip*2, j=jp*2;
        const ull* xi0=(const ull*)&X[i*260];
        const ull* xi1=(const ull*)&X[(i+1)*260];
        const ull* xj0=(const ull*)&X[j*260];
        const ull* xj1=(const ull*)&X[(j+1)*260];
        ull a00=0,a01=0,a10=0,a11=0;
        #pragma unroll 8
        for(int cp=0;cp<128;cp++){
            ull q0=xi0[cp],q1=xi1[cp],p0=xj0[cp],p1=xj1[cp];
            fma2(a00,q0,p0); fma2(a01,q0,p1); fma2(a10,q1,p0); fma2(a11,q1,p1);
        }
        float2 t00=upk(a00),t01=upk(a01),t10=upk(a10),t11=upk(a11);
        int il=i-i0;
        S[il*100+j]      =t00.x+t00.y;
        S[il*100+j+1]    =t01.x+t01.y;
        S[(il+1)*100+j]  =t10.x+t10.y;
        S[(il+1)*100+j+1]=t11.x+t11.y;
    }
    __syncthreads();
    int wd=tid>>5, lane=tid&31;
    for(int r=wd;r<ni;r+=8){
        float mx=-INFINITY;
        for(int j=lane;j<98;j+=32) mx=fmaxf(mx,S[r*100+j]);
        for(int o=16;o>0;o>>=1) mx=fmaxf(mx,__shfl_xor_sync(~0u,mx,o));
        float sum=0.f;
        for(int j=lane;j<98;j+=32){ float e=__expf(S[r*100+j]-mx); S[r*100+j]=e; sum+=e; }
        for(int o=16;o>0;o>>=1) sum+=__shfl_xor_sync(~0u,sum,o);
        float inv=0.0625f/sum;
        float* gs=&g_S[((long)bg*98 + i0+r)*98];
        for(int j=lane;j<98;j+=32) gs[j]=S[r*100+j]*inv;
    }
}

// ---------------- gattn stage 2 ----------------
__global__ void k_gattn2(){
    float* X=dsm;
    float* Ssh=dsm+98*260;
    int bg=blockIdx.x, chunk=blockIdx.y;
    int b=bg>>2, g=bg&3, nx=g>>1, ny=g&1;
    int tid=threadIdx.x;
    for(int e=tid;e<98*256;e+=256){
        int c=e&255, i=e>>8;
        int m=i/49, rr=i%49, w1=rr/7, w2=rr%7;
        int n=b*2+m;
        int pix=(nx*7+w1)*14 + ny*7+w2;
        X[i*260+c]=g_xg2[((long)n*196+pix)*256 + c];
    }
    int i0=chunk*26;
    int ni=min(26,98-i0);
    for(int e=tid;e<ni*98;e+=256){
        int r=e/98, j=e%98;
        Ssh[r*100+j]=g_S[((long)bg*98 + i0+r)*98 + j];
    }
    __syncthreads();
    int npair=ni>>1;
    for(int t=tid;t<13*64;t+=256){
        int ip=t>>6, cq=t&63;
        if(ip>=npair) continue;
        int i=i0+2*ip, c=cq*4;
        ull a00=0,a01=0,a10=0,a11=0;
        const float* S0=&Ssh[(2*ip)*100];
        const float* S1=&Ssh[(2*ip+1)*100];
        for(int j=0;j<98;j++){
            ull s0=pk2(S0[j]), s1=pk2(S1[j]);
            const ull* vp=(const ull*)&X[j*260+c];
            ull v0=vp[0], v1=vp[1];
            fma2(a00,s0,v0); fma2(a01,s0,v1);
            fma2(a10,s1,v0); fma2(a11,s1,v1);
        }
        float2 x00=upk(a00),x01=upk(a01),x10=upk(a10),x11=upk(a11);
        long basep=((long)bg*98+i)*256+c;
        *(float4*)&g_gout[basep]    =make_float4(x00.x,x00.y,x01.x,x01.y);
        *(float4*)&g_gout[basep+256]=make_float4(x10.x,x10.y,x11.x,x11.y);
    }
}

// ---------------- mean over 4 groups ----------------
__global__ void k_qmean(){
    int o=blockIdx.x*blockDim.x+threadIdx.x;
    if(o>=8*NTOK*D) return;
    int c=o&255; int t=o>>8; int i=t%NTOK; int b=t/NTOK;
    float a=0.f;
    for(int g=0;g<4;g++) a+=g_gout[(((long)(b*4+g)*NTOK)+i)*D+c];
    g_qglob[o]=a*0.25f;
}

// ---------------- RPE bias gather ----------------
__global__ void k_bias(const float* __restrict__ rpe){
    int o=blockIdx.x*blockDim.x+threadIdx.x;
    if(o>=NH*NTOK*NTOK) return;
    int j=o%NTOK; int t=o/NTOK; int i=t%NTOK; int h=t/NTOK;
    int mi=i/49, ri=i%49, ai=ri/7, bi=ri%7;
    int mj=j/49, rj=j%49, aj=rj/7, bj=rj%7;
    int idx=(mi-mj+1)*169 + (ai-aj+6)*13 + (bi-bj+6);
    g_biasb[o]=rpe[idx*NH+h];
}

// ---------------- side stream/events ----------------
struct SideStream {
    cudaStream_t s;
    cudaEvent_t eFork, eJoin;
    SideStream(){
        cudaStreamCreateWithFlags(&s, cudaStreamNonBlocking);
        cudaEventCreateWithFlags(&eFork, cudaEventDisableTiming);
        cudaEventCreateWithFlags(&eJoin, cudaEventDisableTiming);
    }
};
static SideStream g_ss;

// ---------------- host ----------------
extern "C" void kernel_launch(void* const* d_in, const int* in_sizes, int n_in,
                              void* d_out, int out_size){
    (void)in_sizes; (void)n_in; (void)out_size;
    const float* x       =(const float*)d_in[0];
    const float* qkv_w   =(const float*)d_in[1];
    const float* qkv_b   =(const float*)d_in[2];
    const float* to_out_w=(const float*)d_in[3];
    const float* rpe     =(const float*)d_in[4];
    const float* fe1_dw  =(const float*)d_in[5];
    const float* fe1_se1 =(const float*)d_in[6];
    const float* fe1_se2 =(const float*)d_in[7];
    const float* fe1_pw  =(const float*)d_in[8];
    const float* fe2_dw  =(const float*)d_in[9];
    const float* fe2_se1 =(const float*)d_in[10];
    const float* fe2_se2 =(const float*)d_in[11];
    const float* fe2_pw  =(const float*)d_in[12];
    float* outp=(float*)d_out;

    float *zb,*xg1,*xg2,*svec;
    __nv_bfloat16 *yh,*yl,*wqh,*wql,*woh,*wol,*aoh,*aol,*bph,*bpl;
    cudaGetSymbolAddress((void**)&yh,   g_Yh);
    cudaGetSymbolAddress((void**)&yl,   g_Yl);
    cudaGetSymbolAddress((void**)&zb,   g_z);
    cudaGetSymbolAddress((void**)&xg1,  g_xg1);
    cudaGetSymbolAddress((void**)&xg2,  g_xg2);
    cudaGetSymbolAddress((void**)&svec, g_svec);
    cudaGetSymbolAddress((void**)&wqh,  g_Wqh);
    cudaGetSymbolAddress((void**)&wql,  g_Wql);
    cudaGetSymbolAddress((void**)&woh,  g_Woh);
    cudaGetSymbolAddress((void**)&wol,  g_Wol);
    cudaGetSymbolAddress((void**)&aoh,  g_aouth);
    cudaGetSymbolAddress((void**)&aol,  g_aoutl);
    cudaGetSymbolAddress((void**)&bph,  g_Bph);
    cudaGetSymbolAddress((void**)&bpl,  g_Bpl);

    const int GATTN_SMEM=(98*260 + 26*100)*4;
    const int WATTN_SMEM=WSM_HALVES*2;
    cudaFuncSetAttribute(k_gattn1, cudaFuncAttributeMaxDynamicSharedMemorySize, GATTN_SMEM);
    cudaFuncSetAttribute(k_gattn2, cudaFuncAttributeMaxDynamicSharedMemorySize, GATTN_SMEM);
    cudaFuncSetAttribute(k_wattn,  cudaFuncAttributeMaxDynamicSharedMemorySize, WATTN_SMEM);

    // ---- fork: independent QKV/weight/bias chain on side stream ----
    cudaEventRecord(g_ss.eFork, 0);
    cudaStreamWaitEvent(g_ss.s, g_ss.eFork, 0);
    k_prep_w<<<(512*256+255)/256,256,0,g_ss.s>>>(qkv_w, wqh, wql, 512);
    k_prep_w<<<(256*256+255)/256,256,0,g_ss.s>>>(to_out_w, woh, wol, 256);
    k_mmagemm<<<dim3(4,MROWS/128),256,0,g_ss.s>>>(x, nullptr, nullptr, wqh, wql, qkv_b, nullptr, 0);
    k_bias<<<(NH*NTOK*NTOK+255)/256,256,0,g_ss.s>>>(rpe);
    cudaEventRecord(g_ss.eJoin, g_ss.s);

    // ---- main chain: conv pyramid + global attention ----
    k_dwconv_nhwc<<<NB*H1*(H1/4)*64/256,256>>>(x, fe1_dw, yh, yl, H1, 1);
    k_semean<<<NB*64,256>>>(yh, yl, H1*H1, 64);
    k_se2<<<NB,256>>>(fe1_se1, fe1_se2, svec, H1*H1, 64);
    k_prep_pwsv<<<dim3(64,NB),256>>>(fe1_pw, svec, bph, bpl);
    k_pwmma<<<dim3(2,25,NB),256>>>(yh, yl, zb, H1*H1);
    k_respool_nhwc<<<NB*H2*H2*64/256,256>>>(x, zb, xg1, H1, H2, 1);
    k_dwconv_nhwc<<<NB*H2*(H2/4)*64/256,256>>>(xg1, fe2_dw, yh, yl, H2, 0);
    k_semean<<<NB*16,256>>>(yh, yl, H2*H2, 16);
    k_se2<<<NB,256>>>(fe2_se1, fe2_se2, svec, H2*H2, 16);
    k_prep_pwsv<<<dim3(64,NB),256>>>(fe2_pw, svec, bph, bpl);
    k_pwmma<<<dim3(2,7,NB),256>>>(yh, yl, zb, H2*H2);
    k_respool_nhwc<<<NB*H3*H3*64/256,256>>>(xg1, zb, xg2, H2, H3, 0);
    k_gattn1<<<dim3(32,4),256,GATTN_SMEM>>>();
    k_gattn2<<<dim3(32,4),256,GATTN_SMEM>>>();
    k_qmean<<<(8*NTOK*D+255)/256,256>>>();

    // ---- join, then window attention + output projection ----
    cudaStreamWaitEvent(0, g_ss.eJoin, 0);
    k_wattn<<<NWIN*NH,256,WATTN_SMEM>>>();
    k_mmagemm<<<dim3(2,MROWS/128),256>>>(nullptr, aoh, aol, woh, wol, nullptr, outp, 1);
}

// round 16
// speedup vs baseline: 1.0299x; 1.0299x over previous
#include <cuda_runtime.h>
#include <cuda_bf16.h>
#include <math.h>
#include <stdint.h>

#define NB   16
#define D    256
#define NH   8
#define NTOK 98
#define NWIN 512
#define SEH  64
#define H1   56
#define H2   28
#define H3   14
#define MROWS 50176

typedef unsigned long long ull;

// ---------------- scratch ----------------
__device__ __align__(16) __nv_bfloat16 g_Yh[(size_t)NB*H1*H1*D];
__device__ __align__(16) __nv_bfloat16 g_Yl[(size_t)NB*H1*H1*D];
__device__ __align__(16) float g_z  [(size_t)NB*H1*H1*D];
__device__ __align__(16) float g_xg1[NB*H2*H2*D];
__device__ __align__(16) float g_xg2[NB*H3*H3*D];
__device__ __align__(16) float g_part[NB*64*D];
__device__ __align__(16) float g_svec [NB*D];
__device__ __align__(16) float g_gout [8*4*NTOK*D];
__device__ __align__(16) float g_qglob[8*NTOK*D];
__device__ __align__(16) float g_kv   [(size_t)MROWS*2*D];
__device__ __align__(16) float g_biasb[NH*NTOK*NTOK];
__device__ __align__(16) float g_S    [32*NTOK*NTOK];
__device__ __align__(16) __nv_bfloat16 g_aouth[(size_t)MROWS*256], g_aoutl[(size_t)MROWS*256];
__device__ __align__(16) __nv_bfloat16 g_Wqh[512*256], g_Wql[512*256];
__device__ __align__(16) __nv_bfloat16 g_Woh[256*256], g_Wol[256*256];

__device__ __forceinline__ float gelu_f(float v){
    return 0.5f*v*(1.0f+erff(v*0.70710678118654752440f));
}
__device__ __forceinline__ long xrow_off(int r){
    int win=r/NTOK, i=r%NTOK;
    int b=win>>6, gx=(win>>3)&7, gy=win&7;
    int m=i/49, rr=i%49, w1=rr/7, w2=rr%7;
    return (((((long)(b*2+m)*8+gx)*8+gy)*7+w1)*7+w2)*256;
}
__device__ __forceinline__ long pix_off(int n, int hp, int wp){
    int gx=hp/7, w1=hp-gx*7, gy=wp/7, w2=wp-gy*7;
    return (((((long)n*8+gx)*8+gy)*7+w1)*7+w2)*256;
}
__device__ __forceinline__ ull pk2(float a){ ull r; asm("mov.b64 %0,{%1,%1};":"=l"(r):"f"(a)); return r; }
__device__ __forceinline__ void fma2(ull&d, ull a, ull b){ asm("fma.rn.f32x2 %0,%1,%2,%0;":"+l"(d):"l"(a),"l"(b)); }
__device__ __forceinline__ float2 upk(ull v){ float2 r; asm("mov.b64 {%0,%1},%2;":"=f"(r.x),"=f"(r.y):"l"(v)); return r; }

__device__ __forceinline__ uint32_t smem_u32(const void* p){
    uint32_t a;
    asm("{ .reg .u64 t; cvta.to.shared.u64 t, %1; cvt.u32.u64 %0, t; }":"=r"(a):"l"(p));
    return a;
}
__device__ __forceinline__ void ldsm4(uint32_t* r, uint32_t a){
    asm volatile("ldmatrix.sync.aligned.m8n8.x4.shared.b16 {%0,%1,%2,%3},[%4];"
        :"=r"(r[0]),"=r"(r[1]),"=r"(r[2]),"=r"(r[3]):"r"(a));
}
__device__ __forceinline__ void ldsm2(uint32_t* r, uint32_t a){
    asm volatile("ldmatrix.sync.aligned.m8n8.x2.shared.b16 {%0,%1},[%2];"
        :"=r"(r[0]),"=r"(r[1]):"r"(a));
}
__device__ __forceinline__ void mma16816(float* d, const uint32_t* a, const uint32_t* b){
    asm volatile("mma.sync.aligned.m16n8k16.row.col.f32.bf16.bf16.f32 "
        "{%0,%1,%2,%3},{%4,%5,%6,%7},{%8,%9},{%0,%1,%2,%3};"
        : "+f"(d[0]),"+f"(d[1]),"+f"(d[2]),"+f"(d[3])
        : "r"(a[0]),"r"(a[1]),"r"(a[2]),"r"(a[3]),"r"(b[0]),"r"(b[1]));
}
__device__ __forceinline__ uint32_t bsplit2(float a, float b, uint32_t& lo){
    __nv_bfloat16 ha=__float2bfloat16(a), hb=__float2bfloat16(b);
    __nv_bfloat16 la=__float2bfloat16(a-__bfloat162float(ha));
    __nv_bfloat16 lb=__float2bfloat16(b-__bfloat162float(hb));
    __nv_bfloat162 h2; h2.x=ha; h2.y=hb;
    __nv_bfloat162 l2; l2.x=la; l2.y=lb;
    lo=*(uint32_t*)&l2;
    return *(uint32_t*)&h2;
}

extern __shared__ float dsm[];

// ---------------- weight transpose + hi/lo split ----------------
__global__ void k_prep_w(const float* __restrict__ W, __nv_bfloat16* __restrict__ Wh,
                         __nv_bfloat16* __restrict__ Wl, int N){
    int o=blockIdx.x*blockDim.x+threadIdx.x;
    if(o>=N*256) return;
    int n=o>>8, k=o&255;
    float v=W[k*N+n];
    __nv_bfloat16 h=__float2bfloat16(v);
    Wh[o]=h;
    Wl[o]=__float2bfloat16(v-__bfloat162float(h));
}

// ---------------- NHWC depthwise 3x3 + gelu, 4 pixels x 4 channels / thread ----------------
__global__ void __launch_bounds__(256) k_dwconv_nhwc(const float* __restrict__ in,
        const float* __restrict__ dw, __nv_bfloat16* __restrict__ Yh,
        __nv_bfloat16* __restrict__ Yl, int HW, int windowed){
    int gid=blockIdx.x*256+threadIdx.x;
    int W4=HW>>2;
    int cq=gid&63; int t=gid>>6;
    int wq=t%W4; t/=W4;
    int hy=t%HW; int n=t/HW;
    if(n>=NB) return;
    int c=cq*4, wx0=wq*4;
    long base = windowed ? (long)n*(64*49*256) : (long)n*HW*HW*256;
    int coff[6];
    #pragma unroll
    for(int u=0;u<6;u++){
        int ww=wx0-1+u;
        if(ww<0||ww>=HW){ coff[u]=-1; }
        else if(windowed){ int gy=ww/7, w2=ww-gy*7; coff[u]=gy*(49*256)+w2*256; }
        else coff[u]=ww*256;
    }
    float acc[4][4]={};
    #pragma unroll
    for(int kh=0;kh<3;kh++){
        int hh=hy+kh-1;
        if(hh<0||hh>=HW) continue;
        long ro;
        if(windowed){ int gx=hh/7, w1=hh-gx*7; ro=base + gx*(8*49*256) + w1*(7*256); }
        else ro=base + (long)hh*HW*256;
        float4 r[6];
        #pragma unroll
        for(int u=0;u<6;u++)
            r[u]=(coff[u]>=0)? *(const float4*)&in[ro+coff[u]+c] : make_float4(0.f,0.f,0.f,0.f);
        float wv[3][4];
        #pragma unroll
        for(int kw=0;kw<3;kw++)
            #pragma unroll
            for(int u=0;u<4;u++) wv[kw][u]=__ldg(&dw[(c+u)*9+kh*3+kw]);
        #pragma unroll
        for(int kw=0;kw<3;kw++){
            #pragma unroll
            for(int px=0;px<4;px++){
                float4 v=r[px+kw];
                acc[px][0]+=v.x*wv[kw][0];
                acc[px][1]+=v.y*wv[kw][1];
                acc[px][2]+=v.z*wv[kw][2];
                acc[px][3]+=v.w*wv[kw][3];
            }
        }
    }
    #pragma unroll
    for(int px=0;px<4;px++){
        __nv_bfloat16 h[4], l[4];
        #pragma unroll
        for(int u=0;u<4;u++){
            float g=gelu_f(acc[px][u]);
            h[u]=__float2bfloat16(g);
            l[u]=__float2bfloat16(g-__bfloat162float(h[u]));
        }
        long ob=((long)n*HW*HW + hy*HW + wx0+px)*256 + c;
        *(ull*)&Yh[ob]=*(ull*)h;
        *(ull*)&Yl[ob]=*(ull*)l;
    }
}

// ---------------- SE stage 1 ----------------
__global__ void k_semean(const __nv_bfloat16* __restrict__ Yh,
        const __nv_bfloat16* __restrict__ Yl, int P, int nch){
    int blk=blockIdx.x;
    int n=blk/nch, ch=blk%nch;
    int t=threadIdx.x;
    int cnt=P/nch;
    const __nv_bfloat16* ph=Yh+((long)n*P + (long)ch*cnt)*256 + t;
    const __nv_bfloat16* pl=Yl+((long)n*P + (long)ch*cnt)*256 + t;
    float s=0.f;
    for(int p=0;p<cnt;p++){
        s += __bfloat162float(ph[(long)p*256]) + __bfloat162float(pl[(long)p*256]);
    }
    g_part[((long)n*64+ch)*256 + t]=s;
}

// ---------------- SE stage 2 ----------------
__global__ void k_se2(const float* __restrict__ se1, const float* __restrict__ se2,
                      float* __restrict__ sv, int P, int nch){
    int n=blockIdx.x;
    __shared__ float sin_[D];
    __shared__ float hid[SEH];
    int t=threadIdx.x;
    float s=0.f;
    for(int j=0;j<nch;j++) s+=g_part[((long)n*64+j)*256 + t];
    sin_[t]=s/(float)P;
    __syncthreads();
    if(t<SEH){
        float a=0.f;
        for(int c=0;c<D;c++) a+=sin_[c]*se1[c*SEH+t];
        hid[t]=gelu_f(a);
    }
    __syncthreads();
    float a=0.f;
    for(int j=0;j<SEH;j++) a+=hid[j]*se2[j*D+t];
    sv[n*D+t]=1.f/(1.f+expf(-a));
}

// ---------------- HMMA pointwise conv ----------------
#define SSTR 40
__global__ void __launch_bounds__(256) k_pwmma(const __nv_bfloat16* __restrict__ Yh,
        const __nv_bfloat16* __restrict__ Yl, const float* __restrict__ pw,
        const float* __restrict__ svg, float* __restrict__ z, int P){
    __shared__ __align__(16) __nv_bfloat16 sAh[128*SSTR];
    __shared__ __align__(16) __nv_bfloat16 sAl[128*SSTR];
    __shared__ __align__(16) __nv_bfloat16 sBh[128*SSTR];
    __shared__ __align__(16) __nv_bfloat16 sBl[128*SSTR];
    int tid=threadIdx.x;
    int wid=tid>>5, lane=tid&31;
    int wm=wid&1, wn=wid>>1;
    int n=blockIdx.z;
    int m0=blockIdx.y*128, n0=blockIdx.x*128;
    const __nv_bfloat16* Yhb=Yh+(long)n*P*256;
    const __nv_bfloat16* Ylb=Yl+(long)n*P*256;
    const float* svp=svg+n*256;
    float* zb=z+(long)n*P*256;

    uint32_t bAh=smem_u32(sAh), bAl=smem_u32(sAl);
    uint32_t bBh=smem_u32(sBh), bBl=smem_u32(sBl);

    float acc[4][4][4];
    #pragma unroll
    for(int i=0;i<4;i++)
        #pragma unroll
        for(int j=0;j<4;j++)
            #pragma unroll
            for(int e=0;e<4;e++) acc[i][j][e]=0.f;

    int arow=lane&15,  acol=(lane>>4)*8;
    int brow=lane&7,   bcol=((lane>>3)&1)*8;
    int lrow=tid>>1, lcb=(tid&1)*16;
    int pr=m0+lrow; if(pr>=P) pr=P-1;

    for(int c=0;c<8;c++){
        int k0=c*32;
        {
            int sb=lrow*SSTR+lcb;
            const __nv_bfloat16* sh=&Yhb[(long)pr*256+k0+lcb];
            const __nv_bfloat16* sl=&Ylb[(long)pr*256+k0+lcb];
            *(uint4*)&sAh[sb]  =*(const uint4*)&sh[0];
            *(uint4*)&sAh[sb+8]=*(const uint4*)&sh[8];
            *(uint4*)&sAl[sb]  =*(const uint4*)&sl[0];
            *(uint4*)&sAl[sb+8]=*(const uint4*)&sl[8];
        }
        {
            int co=n0+lrow;
            const float* ps=&pw[(long)co*256+k0+lcb];
            const float* ss=&svp[k0+lcb];
            __nv_bfloat16 h[16], l[16];
            #pragma unroll
            for(int g=0;g<4;g++){
                float4 v=*(const float4*)&ps[g*4];
                float4 s4=*(const float4*)&ss[g*4];
                float vv[4]={v.x*s4.x,v.y*s4.y,v.z*s4.z,v.w*s4.w};
                #pragma unroll
                for(int u=0;u<4;u++){
                    __nv_bfloat16 hh=__float2bfloat16(vv[u]);
                    h[g*4+u]=hh;
                    l[g*4+u]=__float2bfloat16(vv[u]-__bfloat162float(hh));
                }
            }
            int sb=lrow*SSTR+lcb;
            *(uint4*)&sBh[sb]  =*(const uint4*)&h[0];
            *(uint4*)&sBh[sb+8]=*(const uint4*)&h[8];
            *(uint4*)&sBl[sb]  =*(const uint4*)&l[0];
            *(uint4*)&sBl[sb+8]=*(const uint4*)&l[8];
        }
        __syncthreads();
        #pragma unroll
        for(int ks=0;ks<2;ks++){
            int kk=ks*16;
            uint32_t bh[4][2], bl[4][2];
            #pragma unroll
            for(int nt=0;nt<4;nt++){
                uint32_t boff=(uint32_t)((wn*32+nt*8+brow)*SSTR + kk+bcol)*2u;
                ldsm2(bh[nt], bBh+boff);
                ldsm2(bl[nt], bBl+boff);
            }
            #pragma unroll
            for(int mt=0;mt<4;mt++){
                uint32_t aoff=(uint32_t)((wm*64+mt*16+arow)*SSTR + kk+acol)*2u;
                uint32_t ah[4], al[4];
                ldsm4(ah, bAh+aoff);
                ldsm4(al, bAl+aoff);
                #pragma unroll
                for(int nt=0;nt<4;nt++){
                    mma16816(acc[mt][nt], ah, bh[nt]);
                    mma16816(acc[mt][nt], al, bh[nt]);
                    mma16816(acc[mt][nt], ah, bl[nt]);
                }
            }
        }
        __syncthreads();
    }

    int rl=lane>>2, cl=(lane&3)*2;
    #pragma unroll
    for(int mt=0;mt<4;mt++){
        int r0=wm*64+mt*16+rl, r1=r0+8;
        #pragma unroll
        for(int nt=0;nt<4;nt++){
            int nl=wn*32+nt*8+cl;
            float* d=acc[mt][nt];
            if(m0+r0<P) *(float2*)&zb[(long)(m0+r0)*256 + n0+nl]=make_float2(d[0],d[1]);
            if(m0+r1<P) *(float2*)&zb[(long)(m0+r1)*256 + n0+nl]=make_float2(d[2],d[3]);
        }
    }
}

// ---------------- NHWC residual + maxpool ----------------
__global__ void k_respool_nhwc(const float* __restrict__ xin, const float* __restrict__ z,
        float* __restrict__ out, int Hin, int Hout, int windowed){
    int gid=blockIdx.x*256+threadIdx.x;
    int cq=gid&63; int t=gid>>6;
    int wo=t%Hout; t/=Hout;
    int ho=t%Hout; int n=t/Hout;
    if(n>=NB) return;
    int c=cq*4;
    float4 mx=make_float4(-INFINITY,-INFINITY,-INFINITY,-INFINITY);
    #pragma unroll
    for(int kh=0;kh<3;kh++){
        int hh=2*ho-1+kh;
        if(hh<0||hh>=Hin) continue;
        #pragma unroll
        for(int kw=0;kw<3;kw++){
            int ww=2*wo-1+kw;
            if(ww<0||ww>=Hin) continue;
            long zoff=((long)n*Hin*Hin + hh*Hin+ww)*256 + c;
            float4 a=*(const float4*)&z[zoff];
            long xoff = windowed ? pix_off(n,hh,ww)+c : zoff;
            float4 b=*(const float4*)&xin[xoff];
            mx.x=fmaxf(mx.x,a.x+b.x); mx.y=fmaxf(mx.y,a.y+b.y);
            mx.z=fmaxf(mx.z,a.z+b.z); mx.w=fmaxf(mx.w,a.w+b.w);
        }
    }
    *(float4*)&out[((long)n*Hout*Hout + ho*Hout+wo)*256 + c]=mx;
}

// ---------------- HMMA GEMM (QKV mode0 / to_out mode1) ----------------
__global__ void __launch_bounds__(256) k_mmagemm(const float* __restrict__ Axf,
        const __nv_bfloat16* __restrict__ Ah_, const __nv_bfloat16* __restrict__ Al_,
        const __nv_bfloat16* __restrict__ Wh, const __nv_bfloat16* __restrict__ Wl,
        const float* __restrict__ bias, float* __restrict__ Cb, int mode){
    __shared__ __align__(16) __nv_bfloat16 sAh[128*SSTR];
    __shared__ __align__(16) __nv_bfloat16 sAl[128*SSTR];
    __shared__ __align__(16) __nv_bfloat16 sBh[128*SSTR];
    __shared__ __align__(16) __nv_bfloat16 sBl[128*SSTR];
    __shared__ long roff[128];
    __shared__ float bsh[128];

    int tid=threadIdx.x;
    int wid=tid>>5, lane=tid&31;
    int wm=wid&1, wn=wid>>1;
    int m0=blockIdx.y*128, n0=blockIdx.x*128;

    if(tid<128){
        roff[tid]=xrow_off(m0+tid);
        if(mode==0) bsh[tid]=bias[n0+tid];
    }
    __syncthreads();

    uint32_t bAh=smem_u32(sAh), bAl=smem_u32(sAl);
    uint32_t bBh=smem_u32(sBh), bBl=smem_u32(sBl);

    float acc[4][4][4];
    #pragma unroll
    for(int i=0;i<4;i++)
        #pragma unroll
        for(int j=0;j<4;j++)
            #pragma unroll
            for(int e=0;e<4;e++) acc[i][j][e]=0.f;

    int arow=lane&15,  acol=(lane>>4)*8;
    int brow=lane&7,   bcol=((lane>>3)&1)*8;
    int lrow=tid>>1, lcb=(tid&1)*16;

    for(int c=0;c<8;c++){
        int k0=c*32;
        if(mode==0){
            const float* src=&Axf[roff[lrow]+k0+lcb];
            __nv_bfloat16 h[16], l[16];
            #pragma unroll
            for(int g=0;g<4;g++){
                float4 v=*(const float4*)&src[g*4];
                float vv[4]={v.x,v.y,v.z,v.w};
                #pragma unroll
                for(int u=0;u<4;u++){
                    __nv_bfloat16 hh=__float2bfloat16(vv[u]);
                    h[g*4+u]=hh;
                    l[g*4+u]=__float2bfloat16(vv[u]-__bfloat162float(hh));
                }
            }
            int sb=lrow*SSTR+lcb;
            *(uint4*)&sAh[sb]  =*(const uint4*)&h[0];
            *(uint4*)&sAh[sb+8]=*(const uint4*)&h[8];
            *(uint4*)&sAl[sb]  =*(const uint4*)&l[0];
            *(uint4*)&sAl[sb+8]=*(const uint4*)&l[8];
        }else{
            int sb=lrow*SSTR+lcb;
            const __nv_bfloat16* sh=&Ah_[(long)(m0+lrow)*256+k0+lcb];
            const __nv_bfloat16* sl=&Al_[(long)(m0+lrow)*256+k0+lcb];
            *(uint4*)&sAh[sb]  =*(const uint4*)&sh[0];
            *(uint4*)&sAh[sb+8]=*(const uint4*)&sh[8];
            *(uint4*)&sAl[sb]  =*(const uint4*)&sl[0];
            *(uint4*)&sAl[sb+8]=*(const uint4*)&sl[8];
        }
        {
            const __nv_bfloat16* sh=&Wh[(long)(n0+lrow)*256+k0+lcb];
            const __nv_bfloat16* sl=&Wl[(long)(n0+lrow)*256+k0+lcb];
            int sb=lrow*SSTR+lcb;
            *(uint4*)&sBh[sb]  =*(const uint4*)&sh[0];
            *(uint4*)&sBh[sb+8]=*(const uint4*)&sh[8];
            *(uint4*)&sBl[sb]  =*(const uint4*)&sl[0];
            *(uint4*)&sBl[sb+8]=*(const uint4*)&sl[8];
        }
        __syncthreads();
        #pragma unroll
        for(int ks=0;ks<2;ks++){
            int kk=ks*16;
            uint32_t bh[4][2], bl[4][2];
            #pragma unroll
            for(int nt=0;nt<4;nt++){
                uint32_t boff=(uint32_t)((wn*32+nt*8+brow)*SSTR + kk+bcol)*2u;
                ldsm2(bh[nt], bBh+boff);
                ldsm2(bl[nt], bBl+boff);
            }
            #pragma unroll
            for(int mt=0;mt<4;mt++){
                uint32_t aoff=(uint32_t)((wm*64+mt*16+arow)*SSTR + kk+acol)*2u;
                uint32_t ah[4], al[4];
                ldsm4(ah, bAh+aoff);
                ldsm4(al, bAl+aoff);
                #pragma unroll
                for(int nt=0;nt<4;nt++){
                    mma16816(acc[mt][nt], ah, bh[nt]);
                    mma16816(acc[mt][nt], al, bh[nt]);
                    mma16816(acc[mt][nt], ah, bl[nt]);
                }
            }
        }
        __syncthreads();
    }

    int rl=lane>>2, cl=(lane&3)*2;
    #pragma unroll
    for(int mt=0;mt<4;mt++){
        int r0=wm*64+mt*16+rl, r1=r0+8;
        #pragma unroll
        for(int nt=0;nt<4;nt++){
            int nl=wn*32+nt*8+cl;
            float* d=acc[mt][nt];
            if(mode==0){
                float b0=bsh[nl], b1=bsh[nl+1];
                float* p0=&g_kv[(long)(m0+r0)*512 + n0+nl];
                float* p1=&g_kv[(long)(m0+r1)*512 + n0+nl];
                p0[0]=d[0]+b0; p0[1]=d[1]+b1;
                p1[0]=d[2]+b0; p1[1]=d[3]+b1;
            }else{
                float* p0=&Cb[roff[r0] + n0+nl];
                float* p1=&Cb[roff[r1] + n0+nl];
                p0[0]=d[0]; p0[1]=d[1];
                p1[0]=d[2]; p1[1]=d[3];
            }
        }
    }
}

// ---------------- HMMA window attention (register-resident P, pad-only zeroing) ----------------
#define QSTR 40
#define PSTR 120
#define OQH 0
#define OQL (OQH+112*QSTR)
#define OKH (OQL+112*QSTR)
#define OKL (OKH+112*QSTR)
#define OVH (OKL+112*QSTR)
#define OVL (OVH+32*PSTR)
#define WSM_HALVES (OVL+32*PSTR)
__global__ void __launch_bounds__(256,2) k_wattn(){
    __nv_bfloat16* sb=(__nv_bfloat16*)dsm;
    int wh=blockIdx.x; int head=wh&7; int win=wh>>3; int b=win>>6;
    int tid=threadIdx.x, wid=tid>>5, lane=tid&31;
    const float scale=0.17677669529663687f;

    // pad-only zeroing: q/k rows 98..111 (4 arrays x 70 uint4) and
    // vT cols 96..119 (2 arrays x 32 rows x 3 uint4)
    for(int e=tid;e<280;e+=256){
        int arr=e/70, rem=e%70;
        *(uint4*)&sb[(uint32_t)arr*112*QSTR + 98*QSTR + rem*8]=make_uint4(0,0,0,0);
    }
    for(int e=tid;e<192;e+=256){
        int arr=e/96, rem=e%96;
        int c=rem/3, g=rem%3;
        *(uint4*)&sb[(uint32_t)OVH + (uint32_t)arr*32*PSTR + c*PSTR + 96 + g*8]=make_uint4(0,0,0,0);
    }
    __syncthreads();

    for(int e=tid;e<224;e+=256){
        int row=e>>1, half=(e&1)*16;
        if(row<98){
            const float* qs=&g_qglob[((long)b*98+row)*256 + head*32 + half];
            const float* ks=&g_kv[(((long)win*98+row))*512 + head*32 + half];
            uint32_t qh[8], ql[8], kh[8], kl[8];
            #pragma unroll
            for(int u=0;u<8;u++){
                float q0=qs[2*u]*scale, q1=qs[2*u+1]*scale;
                qh[u]=bsplit2(q0,q1,ql[u]);
                kh[u]=bsplit2(ks[2*u],ks[2*u+1],kl[u]);
            }
            int sbo=row*QSTR+half;
            *(uint4*)&sb[OQH+sbo]  =*(uint4*)&qh[0];
            *(uint4*)&sb[OQH+sbo+8]=*(uint4*)&qh[4];
            *(uint4*)&sb[OQL+sbo]  =*(uint4*)&ql[0];
            *(uint4*)&sb[OQL+sbo+8]=*(uint4*)&ql[4];
            *(uint4*)&sb[OKH+sbo]  =*(uint4*)&kh[0];
            *(uint4*)&sb[OKH+sbo+8]=*(uint4*)&kh[4];
            *(uint4*)&sb[OKL+sbo]  =*(uint4*)&kl[0];
            *(uint4*)&sb[OKL+sbo+8]=*(uint4*)&kl[4];
        }
    }
    for(int e=tid;e<196;e+=256){
        int row=e>>1, half=(e&1)*16;
        const float* vs=&g_kv[(((long)win*98+row))*512 + 256 + head*32 + half];
        #pragma unroll
        for(int u=0;u<16;u++){
            float vv=vs[u];
            __nv_bfloat16 h=__float2bfloat16(vv);
            __nv_bfloat16 l=__float2bfloat16(vv-__bfloat162float(h));
            int c=half+u;
            sb[OVH+c*PSTR+row]=h;
            sb[OVL+c*PSTR+row]=l;
        }
    }
    __syncthreads();

    uint32_t base=smem_u32(sb);
    int arow=lane&15, acol=(lane>>4)*8;
    int brow=lane&7,  bcol=((lane>>3)&1)*8;
    int rl=lane>>2, cl=(lane&3)*2;

    if(wid<7){
        float sacc[13][4];
        #pragma unroll
        for(int nt=0;nt<13;nt++){
            #pragma unroll
            for(int e2=0;e2<4;e2++) sacc[nt][e2]=0.f;
        }
        #pragma unroll
        for(int kc=0;kc<2;kc++){
            int kk=kc*16;
            uint32_t aoff=(uint32_t)((wid*16+arow)*QSTR + kk+acol)*2u;
            uint32_t ah[4], al[4];
            ldsm4(ah, base+(OQH*2u)+aoff);
            ldsm4(al, base+(OQL*2u)+aoff);
            #pragma unroll
            for(int nt=0;nt<13;nt++){
                uint32_t boff=(uint32_t)((nt*8+brow)*QSTR + kk+bcol)*2u;
                uint32_t bh[2], bl[2];
                ldsm2(bh, base+(OKH*2u)+boff);
                ldsm2(bl, base+(OKL*2u)+boff);
                mma16816(sacc[nt], ah, bh);
                mma16816(sacc[nt], al, bh);
                mma16816(sacc[nt], ah, bl);
            }
        }
        int r0=wid*16+rl, r1=r0+8;
        const float* bbase=&g_biasb[(long)head*9604];
        #pragma unroll
        for(int nt=0;nt<13;nt++){
            int j0=nt*8+cl;
            if(j0>=98){
                sacc[nt][0]=-1e30f; sacc[nt][1]=-1e30f;
                sacc[nt][2]=-1e30f; sacc[nt][3]=-1e30f;
            }else{
                if(r0<98){
                    float2 bb=*(const float2*)&bbase[r0*98+j0];
                    sacc[nt][0]+=bb.x; sacc[nt][1]+=bb.y;
                }
                if(r1<98){
                    float2 bb=*(const float2*)&bbase[r1*98+j0];
                    sacc[nt][2]+=bb.x; sacc[nt][3]+=bb.y;
                }
            }
        }
        float mx0=-1e30f, mx1=-1e30f;
        #pragma unroll
        for(int nt=0;nt<13;nt++){
            mx0=fmaxf(mx0,fmaxf(sacc[nt][0],sacc[nt][1]));
            mx1=fmaxf(mx1,fmaxf(sacc[nt][2],sacc[nt][3]));
        }
        mx0=fmaxf(mx0,__shfl_xor_sync(~0u,mx0,1)); mx0=fmaxf(mx0,__shfl_xor_sync(~0u,mx0,2));
        mx1=fmaxf(mx1,__shfl_xor_sync(~0u,mx1,1)); mx1=fmaxf(mx1,__shfl_xor_sync(~0u,mx1,2));
        float sum0=0.f, sum1=0.f;
        #pragma unroll
        for(int nt=0;nt<13;nt++){
            sacc[nt][0]=__expf(sacc[nt][0]-mx0); sum0+=sacc[nt][0];
            sacc[nt][1]=__expf(sacc[nt][1]-mx0); sum0+=sacc[nt][1];
            sacc[nt][2]=__expf(sacc[nt][2]-mx1); sum1+=sacc[nt][2];
            sacc[nt][3]=__expf(sacc[nt][3]-mx1); sum1+=sacc[nt][3];
        }
        sum0+=__shfl_xor_sync(~0u,sum0,1); sum0+=__shfl_xor_sync(~0u,sum0,2);
        sum1+=__shfl_xor_sync(~0u,sum1,1); sum1+=__shfl_xor_sync(~0u,sum1,2);
        float inv0=1.f/sum0, inv1=1.f/sum1;

        uint32_t phi[7][4], plo[7][4];
        #pragma unroll
        for(int t7=0;t7<7;t7++){
            int nt0=2*t7, nt1=2*t7+1;
            phi[t7][0]=bsplit2(sacc[nt0][0]*inv0, sacc[nt0][1]*inv0, plo[t7][0]);
            phi[t7][1]=bsplit2(sacc[nt0][2]*inv1, sacc[nt0][3]*inv1, plo[t7][1]);
            if(nt1<13){
                phi[t7][2]=bsplit2(sacc[nt1][0]*inv0, sacc[nt1][1]*inv0, plo[t7][2]);
                phi[t7][3]=bsplit2(sacc[nt1][2]*inv1, sacc[nt1][3]*inv1, plo[t7][3]);
            }else{
                phi[t7][2]=0u; plo[t7][2]=0u;
                phi[t7][3]=0u; plo[t7][3]=0u;
            }
        }

        float oacc[4][4];
        #pragma unroll
        for(int nt=0;nt<4;nt++)
            #pragma unroll
            for(int e2=0;e2<4;e2++) oacc[nt][e2]=0.f;
        #pragma unroll
        for(int t7=0;t7<7;t7++){
            int kk=t7*16;
            #pragma unroll
            for(int nt=0;nt<4;nt++){
                uint32_t boff=(uint32_t)((nt*8+brow)*PSTR + kk+bcol)*2u;
                uint32_t bh[2], bl[2];
                ldsm2(bh, base+(OVH*2u)+boff);
                ldsm2(bl, base+(OVL*2u)+boff);
                mma16816(oacc[nt], phi[t7], bh);
                mma16816(oacc[nt], plo[t7], bh);
                mma16816(oacc[nt], phi[t7], bl);
            }
        }
        #pragma unroll
        for(int nt=0;nt<4;nt++){
            int c=nt*8+cl;
            uint32_t lo0, lo1;
            uint32_t hi0=bsplit2(oacc[nt][0], oacc[nt][1], lo0);
            uint32_t hi1=bsplit2(oacc[nt][2], oacc[nt][3], lo1);
            if(r0<98){
                long bse=((long)win*98+r0)*256 + head*32 + c;
                *(uint32_t*)&g_aouth[bse]=hi0;
                *(uint32_t*)&g_aoutl[bse]=lo0;
            }
            if(r1<98){
                long bse=((long)win*98+r1)*256 + head*32 + c;
                *(uint32_t*)&g_aouth[bse]=hi1;
                *(uint32_t*)&g_aoutl[bse]=lo1;
            }
        }
    }
}

// ---------------- gattn stage 1 ----------------
__global__ void k_gattn1(){
    float* X=dsm;
    float* S=dsm+98*260;
    int bg=blockIdx.x, chunk=blockIdx.y;
    int b=bg>>2, g=bg&3, nx=g>>1, ny=g&1;
    int tid=threadIdx.x;
    for(int e=tid;e<98*256;e+=256){
        int c=e&255, i=e>>8;
        int m=i/49, rr=i%49, w1=rr/7, w2=rr%7;
        int n=b*2+m;
        int pix=(nx*7+w1)*14 + ny*7+w2;
        X[i*260+c]=g_xg2[((long)n*196+pix)*256 + c];
    }
    __syncthreads();
    int i0=chunk*26;
    int ni=min(26,98-i0);
    int npair=ni>>1;
    for(int t=tid;t<13*49;t+=256){
        int ip=t/49, jp=t%49;
        if(ip>=npair) continue;
        int i=i0+ip*2, j=jp*2;
        const ull* xi0=(const ull*)&X[i*260];
        const ull* xi1=(const ull*)&X[(i+1)*260];
        const ull* xj0=(const ull*)&X[j*260];
        const ull* xj1=(const ull*)&X[(j+1)*260];
        ull a00=0,a01=0,a10=0,a11=0;
        #pragma unroll 8
        for(int cp=0;cp<128;cp++){
            ull q0=xi0[cp],q1=xi1[cp],p0=xj0[cp],p1=xj1[cp];
            fma2(a00,q0,p0); fma2(a01,q0,p1); fma2(a10,q1,p0); fma2(a11,q1,p1);
        }
        float2 t00=upk(a00),t01=upk(a01),t10=upk(a10),t11=upk(a11);
        int il=i-i0;
        S[il*100+j]      =t00.x+t00.y;
        S[il*100+j+1]    =t01.x+t01.y;
        S[(il+1)*100+j]  =t10.x+t10.y;
        S[(il+1)*100+j+1]=t11.x+t11.y;
    }
    __syncthreads();
    int wd=tid>>5, lane=tid&31;
    for(int r=wd;r<ni;r+=8){
        float mx=-INFINITY;
        for(int j=lane;j<98;j+=32) mx=fmaxf(mx,S[r*100+j]);
        for(int o=16;o>0;o>>=1) mx=fmaxf(mx,__shfl_xor_sync(~0u,mx,o));
        float sum=0.f;
        for(int j=lane;j<98;j+=32){ float e=__expf(S[r*100+j]-mx); S[r*100+j]=e; sum+=e; }
        for(int o=16;o>0;o>>=1) sum+=__shfl_xor_sync(~0u,sum,o);
        float inv=0.0625f/sum;
        float* gs=&g_S[((long)bg*98 + i0+r)*98];
        for(int j=lane;j<98;j+=32) gs[j]=S[r*100+j]*inv;
    }
}

// ---------------- gattn stage 2 ----------------
__global__ void k_gattn2(){
    float* X=dsm;
    float* Ssh=dsm+98*260;
    int bg=blockIdx.x, chunk=blockIdx.y;
    int b=bg>>2, g=bg&3, nx=g>>1, ny=g&1;
    int tid=threadIdx.x;
    for(int e=tid;e<98*256;e+=256){
        int c=e&255, i=e>>8;
        int m=i/49, rr=i%49, w1=rr/7, w2=rr%7;
        int n=b*2+m;
        int pix=(nx*7+w1)*14 + ny*7+w2;
        X[i*260+c]=g_xg2[((long)n*196+pix)*256 + c];
    }
    int i0=chunk*26;
    int ni=min(26,98-i0);
    for(int e=tid;e<ni*98;e+=256){
        int r=e/98, j=e%98;
        Ssh[r*100+j]=g_S[((long)bg*98 + i0+r)*98 + j];
    }
    __syncthreads();
    int npair=ni>>1;
    for(int t=tid;t<13*64;t+=256){
        int ip=t>>6, cq=t&63;
        if(ip>=npair) continue;
        int i=i0+2*ip, c=cq*4;
        ull a00=0,a01=0,a10=0,a11=0;
        const float* S0=&Ssh[(2*ip)*100];
        const float* S1=&Ssh[(2*ip+1)*100];
        for(int j=0;j<98;j++){
            ull s0=pk2(S0[j]), s1=pk2(S1[j]);
            const ull* vp=(const ull*)&X[j*260+c];
            ull v0=vp[0], v1=vp[1];
            fma2(a00,s0,v0); fma2(a01,s0,v1);
            fma2(a10,s1,v0); fma2(a11,s1,v1);
        }
        float2 x00=upk(a00),x01=upk(a01),x10=upk(a10),x11=upk(a11);
        long basep=((long)bg*98+i)*256+c;
        *(float4*)&g_gout[basep]    =make_float4(x00.x,x00.y,x01.x,x01.y);
        *(float4*)&g_gout[basep+256]=make_float4(x10.x,x10.y,x11.x,x11.y);
    }
}

// ---------------- mean over 4 groups ----------------
__global__ void k_qmean(){
    int o=blockIdx.x*blockDim.x+threadIdx.x;
    if(o>=8*NTOK*D) return;
    int c=o&255; int t=o>>8; int i=t%NTOK; int b=t/NTOK;
    float a=0.f;
    for(int g=0;g<4;g++) a+=g_gout[(((long)(b*4+g)*NTOK)+i)*D+c];
    g_qglob[o]=a*0.25f;
}

// ---------------- RPE bias gather ----------------
__global__ void k_bias(const float* __restrict__ rpe){
    int o=blockIdx.x*blockDim.x+threadIdx.x;
    if(o>=NH*NTOK*NTOK) return;
    int j=o%NTOK; int t=o/NTOK; int i=t%NTOK; int h=t/NTOK;
    int mi=i/49, ri=i%49, ai=ri/7, bi=ri%7;
    int mj=j/49, rj=j%49, aj=rj/7, bj=rj%7;
    int idx=(mi-mj+1)*169 + (ai-aj+6)*13 + (bi-bj+6);
    g_biasb[o]=rpe[idx*NH+h];
}

// ---------------- side stream/events ----------------
struct SideStream {
    cudaStream_t s;
    cudaEvent_t eFork, eJoin;
    SideStream(){
        cudaStreamCreateWithFlags(&s, cudaStreamNonBlocking);
        cudaEventCreateWithFlags(&eFork, cudaEventDisableTiming);
        cudaEventCreateWithFlags(&eJoin, cudaEventDisableTiming);
    }
};
static SideStream g_ss;

// ---------------- host ----------------
extern "C" void kernel_launch(void* const* d_in, const int* in_sizes, int n_in,
                              void* d_out, int out_size){
    (void)in_sizes; (void)n_in; (void)out_size;
    const float* x       =(const float*)d_in[0];
    const float* qkv_w   =(const float*)d_in[1];
    const float* qkv_b   =(const float*)d_in[2];
    const float* to_out_w=(const float*)d_in[3];
    const float* rpe     =(const float*)d_in[4];
    const float* fe1_dw  =(const float*)d_in[5];
    const float* fe1_se1 =(const float*)d_in[6];
    const float* fe1_se2 =(const float*)d_in[7];
    const float* fe1_pw  =(const float*)d_in[8];
    const float* fe2_dw  =(const float*)d_in[9];
    const float* fe2_se1 =(const float*)d_in[10];
    const float* fe2_se2 =(const float*)d_in[11];
    const float* fe2_pw  =(const float*)d_in[12];
    float* outp=(float*)d_out;

    float *zb,*xg1,*xg2,*svec;
    __nv_bfloat16 *yh,*yl,*wqh,*wql,*woh,*wol,*aoh,*aol;
    cudaGetSymbolAddress((void**)&yh,   g_Yh);
    cudaGetSymbolAddress((void**)&yl,   g_Yl);
    cudaGetSymbolAddress((void**)&zb,   g_z);
    cudaGetSymbolAddress((void**)&xg1,  g_xg1);
    cudaGetSymbolAddress((void**)&xg2,  g_xg2);
    cudaGetSymbolAddress((void**)&svec, g_svec);
    cudaGetSymbolAddress((void**)&wqh,  g_Wqh);
    cudaGetSymbolAddress((void**)&wql,  g_Wql);
    cudaGetSymbolAddress((void**)&woh,  g_Woh);
    cudaGetSymbolAddress((void**)&wol,  g_Wol);
    cudaGetSymbolAddress((void**)&aoh,  g_aouth);
    cudaGetSymbolAddress((void**)&aol,  g_aoutl);

    const int GATTN_SMEM=(98*260 + 26*100)*4;
    const int WATTN_SMEM=WSM_HALVES*2;
    cudaFuncSetAttribute(k_gattn1, cudaFuncAttributeMaxDynamicSharedMemorySize, GATTN_SMEM);
    cudaFuncSetAttribute(k_gattn2, cudaFuncAttributeMaxDynamicSharedMemorySize, GATTN_SMEM);
    cudaFuncSetAttribute(k_wattn,  cudaFuncAttributeMaxDynamicSharedMemorySize, WATTN_SMEM);

    // ---- fork: independent QKV/weight/bias chain on side stream ----
    cudaEventRecord(g_ss.eFork, 0);
    cudaStreamWaitEvent(g_ss.s, g_ss.eFork, 0);
    k_prep_w<<<(512*256+255)/256,256,0,g_ss.s>>>(qkv_w, wqh, wql, 512);
    k_prep_w<<<(256*256+255)/256,256,0,g_ss.s>>>(to_out_w, woh, wol, 256);
    k_mmagemm<<<dim3(4,MROWS/128),256,0,g_ss.s>>>(x, nullptr, nullptr, wqh, wql, qkv_b, nullptr, 0);
    k_bias<<<(NH*NTOK*NTOK+255)/256,256,0,g_ss.s>>>(rpe);
    cudaEventRecord(g_ss.eJoin, g_ss.s);

    // ---- main chain: conv pyramid + global attention ----
    k_dwconv_nhwc<<<NB*H1*(H1/4)*64/256,256>>>(x, fe1_dw, yh, yl, H1, 1);
    k_semean<<<NB*64,256>>>(yh, yl, H1*H1, 64);
    k_se2<<<NB,256>>>(fe1_se1, fe1_se2, svec, H1*H1, 64);
    k_pwmma<<<dim3(2,25,NB),256>>>(yh, yl, fe1_pw, svec, zb, H1*H1);
    k_respool_nhwc<<<NB*H2*H2*64/256,256>>>(x, zb, xg1, H1, H2, 1);
    k_dwconv_nhwc<<<NB*H2*(H2/4)*64/256,256>>>(xg1, fe2_dw, yh, yl, H2, 0);
    k_semean<<<NB*16,256>>>(yh, yl, H2*H2, 16);
    k_se2<<<NB,256>>>(fe2_se1, fe2_se2, svec, H2*H2, 16);
    k_pwmma<<<dim3(2,7,NB),256>>>(yh, yl, fe2_pw, svec, zb, H2*H2);
    k_respool_nhwc<<<NB*H3*H3*64/256,256>>>(xg1, zb, xg2, H2, H3, 0);
    k_gattn1<<<dim3(32,4),256,GATTN_SMEM>>>();
    k_gattn2<<<dim3(32,4),256,GATTN_SMEM>>>();
    k_qmean<<<(8*NTOK*D+255)/256,256>>>();

    // ---- join, then window attention + output projection ----
    cudaStreamWaitEvent(0, g_ss.eJoin, 0);
    k_wattn<<<NWIN*NH,256,WATTN_SMEM>>>();
    k_mmagemm<<<dim3(2,MROWS/128),256>>>(nullptr, aoh, aol, woh, wol, nullptr, outp, 1);
}

// round 17
// speedup vs baseline: 1.1071x; 1.0750x over previous
#include <cuda_runtime.h>
#include <cuda_bf16.h>
#include <math.h>
#include <stdint.h>

#define NB   16
#define D    256
#define NH   8
#define NTOK 98
#define NWIN 512
#define SEH  64
#define H1   56
#define H2   28
#define H3   14
#define MROWS 50176

typedef unsigned long long ull;

// ---------------- scratch ----------------
__device__ __align__(16) __nv_bfloat16 g_Yh[(size_t)NB*H1*H1*D];
__device__ __align__(16) __nv_bfloat16 g_Yl[(size_t)NB*H1*H1*D];
__device__ __align__(16) float g_z  [(size_t)NB*H1*H1*D];
__device__ __align__(16) float g_xg1[NB*H2*H2*D];
__device__ __align__(16) float g_xg2[NB*H3*H3*D];
__device__ __align__(16) float g_part[NB*64*D];
__device__ __align__(16) float g_svec [NB*D];
__device__ __align__(16) float g_gout [8*4*NTOK*D];
__device__ __align__(16) float g_qglob[8*NTOK*D];
__device__ __align__(16) float g_kv   [(size_t)MROWS*2*D];
__device__ __align__(16) float g_biasb[NH*NTOK*NTOK];
__device__ __align__(16) float g_S    [32*NTOK*NTOK];
__device__ __align__(16) __nv_bfloat16 g_aouth[(size_t)MROWS*256], g_aoutl[(size_t)MROWS*256];
__device__ __align__(16) __nv_bfloat16 g_Wqh[512*256], g_Wql[512*256];
__device__ __align__(16) __nv_bfloat16 g_Woh[256*256], g_Wol[256*256];

__device__ __forceinline__ float gelu_f(float v){
    return 0.5f*v*(1.0f+erff(v*0.70710678118654752440f));
}
__device__ __forceinline__ long xrow_off(int r){
    int win=r/NTOK, i=r%NTOK;
    int b=win>>6, gx=(win>>3)&7, gy=win&7;
    int m=i/49, rr=i%49, w1=rr/7, w2=rr%7;
    return (((((long)(b*2+m)*8+gx)*8+gy)*7+w1)*7+w2)*256;
}
__device__ __forceinline__ long pix_off(int n, int hp, int wp){
    int gx=hp/7, w1=hp-gx*7, gy=wp/7, w2=wp-gy*7;
    return (((((long)n*8+gx)*8+gy)*7+w1)*7+w2)*256;
}
__device__ __forceinline__ ull pk2(float a){ ull r; asm("mov.b64 %0,{%1,%1};":"=l"(r):"f"(a)); return r; }
__device__ __forceinline__ void fma2(ull&d, ull a, ull b){ asm("fma.rn.f32x2 %0,%1,%2,%0;":"+l"(d):"l"(a),"l"(b)); }
__device__ __forceinline__ float2 upk(ull v){ float2 r; asm("mov.b64 {%0,%1},%2;":"=f"(r.x),"=f"(r.y):"l"(v)); return r; }

__device__ __forceinline__ uint32_t smem_u32(const void* p){
    uint32_t a;
    asm("{ .reg .u64 t; cvta.to.shared.u64 t, %1; cvt.u32.u64 %0, t; }":"=r"(a):"l"(p));
    return a;
}
__device__ __forceinline__ void ldsm4(uint32_t* r, uint32_t a){
    asm volatile("ldmatrix.sync.aligned.m8n8.x4.shared.b16 {%0,%1,%2,%3},[%4];"
        :"=r"(r[0]),"=r"(r[1]),"=r"(r[2]),"=r"(r[3]):"r"(a));
}
__device__ __forceinline__ void ldsm2(uint32_t* r, uint32_t a){
    asm volatile("ldmatrix.sync.aligned.m8n8.x2.shared.b16 {%0,%1},[%2];"
        :"=r"(r[0]),"=r"(r[1]):"r"(a));
}
__device__ __forceinline__ void mma16816(float* d, const uint32_t* a, const uint32_t* b){
    asm volatile("mma.sync.aligned.m16n8k16.row.col.f32.bf16.bf16.f32 "
        "{%0,%1,%2,%3},{%4,%5,%6,%7},{%8,%9},{%0,%1,%2,%3};"
        : "+f"(d[0]),"+f"(d[1]),"+f"(d[2]),"+f"(d[3])
        : "r"(a[0]),"r"(a[1]),"r"(a[2]),"r"(a[3]),"r"(b[0]),"r"(b[1]));
}
__device__ __forceinline__ uint32_t bsplit2(float a, float b, uint32_t& lo){
    __nv_bfloat16 ha=__float2bfloat16(a), hb=__float2bfloat16(b);
    __nv_bfloat16 la=__float2bfloat16(a-__bfloat162float(ha));
    __nv_bfloat16 lb=__float2bfloat16(b-__bfloat162float(hb));
    __nv_bfloat162 h2; h2.x=ha; h2.y=hb;
    __nv_bfloat162 l2; l2.x=la; l2.y=lb;
    lo=*(uint32_t*)&l2;
    return *(uint32_t*)&h2;
}
__device__ __forceinline__ void cpa16(uint32_t d, const void* s){
    asm volatile("cp.async.ca.shared.global [%0], [%1], 16;"::"r"(d),"l"(s):"memory");
}
#define CPCOMMIT() asm volatile("cp.async.commit_group;":::"memory")
#define CPWAIT0()  asm volatile("cp.async.wait_group 0;":::"memory")

extern __shared__ float dsm[];

// ---------------- weight transpose + hi/lo split ----------------
__global__ void k_prep_w(const float* __restrict__ W, __nv_bfloat16* __restrict__ Wh,
                         __nv_bfloat16* __restrict__ Wl, int N){
    int o=blockIdx.x*blockDim.x+threadIdx.x;
    if(o>=N*256) return;
    int n=o>>8, k=o&255;
    float v=W[k*N+n];
    __nv_bfloat16 h=__float2bfloat16(v);
    Wh[o]=h;
    Wl[o]=__float2bfloat16(v-__bfloat162float(h));
}

// ---------------- NHWC depthwise 3x3 + gelu ----------------
__global__ void __launch_bounds__(256) k_dwconv_nhwc(const float* __restrict__ in,
        const float* __restrict__ dw, __nv_bfloat16* __restrict__ Yh,
        __nv_bfloat16* __restrict__ Yl, int HW, int windowed){
    int gid=blockIdx.x*256+threadIdx.x;
    int W4=HW>>2;
    int cq=gid&63; int t=gid>>6;
    int wq=t%W4; t/=W4;
    int hy=t%HW; int n=t/HW;
    if(n>=NB) return;
    int c=cq*4, wx0=wq*4;
    long base = windowed ? (long)n*(64*49*256) : (long)n*HW*HW*256;
    int coff[6];
    #pragma unroll
    for(int u=0;u<6;u++){
        int ww=wx0-1+u;
        if(ww<0||ww>=HW){ coff[u]=-1; }
        else if(windowed){ int gy=ww/7, w2=ww-gy*7; coff[u]=gy*(49*256)+w2*256; }
        else coff[u]=ww*256;
    }
    float acc[4][4]={};
    #pragma unroll
    for(int kh=0;kh<3;kh++){
        int hh=hy+kh-1;
        if(hh<0||hh>=HW) continue;
        long ro;
        if(windowed){ int gx=hh/7, w1=hh-gx*7; ro=base + gx*(8*49*256) + w1*(7*256); }
        else ro=base + (long)hh*HW*256;
        float4 r[6];
        #pragma unroll
        for(int u=0;u<6;u++)
            r[u]=(coff[u]>=0)? *(const float4*)&in[ro+coff[u]+c] : make_float4(0.f,0.f,0.f,0.f);
        float wv[3][4];
        #pragma unroll
        for(int kw=0;kw<3;kw++)
            #pragma unroll
            for(int u=0;u<4;u++) wv[kw][u]=__ldg(&dw[(c+u)*9+kh*3+kw]);
        #pragma unroll
        for(int kw=0;kw<3;kw++){
            #pragma unroll
            for(int px=0;px<4;px++){
                float4 v=r[px+kw];
                acc[px][0]+=v.x*wv[kw][0];
                acc[px][1]+=v.y*wv[kw][1];
                acc[px][2]+=v.z*wv[kw][2];
                acc[px][3]+=v.w*wv[kw][3];
            }
        }
    }
    #pragma unroll
    for(int px=0;px<4;px++){
        __nv_bfloat16 h[4], l[4];
        #pragma unroll
        for(int u=0;u<4;u++){
            float g=gelu_f(acc[px][u]);
            h[u]=__float2bfloat16(g);
            l[u]=__float2bfloat16(g-__bfloat162float(h[u]));
        }
        long ob=((long)n*HW*HW + hy*HW + wx0+px)*256 + c;
        *(ull*)&Yh[ob]=*(ull*)h;
        *(ull*)&Yl[ob]=*(ull*)l;
    }
}

// ---------------- SE stage 1 ----------------
__global__ void k_semean(const __nv_bfloat16* __restrict__ Yh,
        const __nv_bfloat16* __restrict__ Yl, int P, int nch){
    int blk=blockIdx.x;
    int n=blk/nch, ch=blk%nch;
    int t=threadIdx.x;
    int cnt=P/nch;
    const __nv_bfloat16* ph=Yh+((long)n*P + (long)ch*cnt)*256 + t;
    const __nv_bfloat16* pl=Yl+((long)n*P + (long)ch*cnt)*256 + t;
    float s=0.f;
    for(int p=0;p<cnt;p++){
        s += __bfloat162float(ph[(long)p*256]) + __bfloat162float(pl[(long)p*256]);
    }
    g_part[((long)n*64+ch)*256 + t]=s;
}

// ---------------- SE stage 2 ----------------
__global__ void k_se2(const float* __restrict__ se1, const float* __restrict__ se2,
                      float* __restrict__ sv, int P, int nch){
    int n=blockIdx.x;
    __shared__ float sin_[D];
    __shared__ float hid[SEH];
    int t=threadIdx.x;
    float s=0.f;
    for(int j=0;j<nch;j++) s+=g_part[((long)n*64+j)*256 + t];
    sin_[t]=s/(float)P;
    __syncthreads();
    if(t<SEH){
        float a=0.f;
        for(int c=0;c<D;c++) a+=sin_[c]*se1[c*SEH+t];
        hid[t]=gelu_f(a);
    }
    __syncthreads();
    float a=0.f;
    for(int j=0;j<SEH;j++) a+=hid[j]*se2[j*D+t];
    sv[n*D+t]=1.f/(1.f+expf(-a));
}

// ---------------- HMMA pointwise conv ----------------
#define SSTR 40
__global__ void __launch_bounds__(256) k_pwmma(const __nv_bfloat16* __restrict__ Yh,
        const __nv_bfloat16* __restrict__ Yl, const float* __restrict__ pw,
        const float* __restrict__ svg, float* __restrict__ z, int P){
    __shared__ __align__(16) __nv_bfloat16 sAh[128*SSTR];
    __shared__ __align__(16) __nv_bfloat16 sAl[128*SSTR];
    __shared__ __align__(16) __nv_bfloat16 sBh[128*SSTR];
    __shared__ __align__(16) __nv_bfloat16 sBl[128*SSTR];
    int tid=threadIdx.x;
    int wid=tid>>5, lane=tid&31;
    int wm=wid&1, wn=wid>>1;
    int n=blockIdx.z;
    int m0=blockIdx.y*128, n0=blockIdx.x*128;
    const __nv_bfloat16* Yhb=Yh+(long)n*P*256;
    const __nv_bfloat16* Ylb=Yl+(long)n*P*256;
    const float* svp=svg+n*256;
    float* zb=z+(long)n*P*256;

    uint32_t bAh=smem_u32(sAh), bAl=smem_u32(sAl);
    uint32_t bBh=smem_u32(sBh), bBl=smem_u32(sBl);

    float acc[4][4][4];
    #pragma unroll
    for(int i=0;i<4;i++)
        #pragma unroll
        for(int j=0;j<4;j++)
            #pragma unroll
            for(int e=0;e<4;e++) acc[i][j][e]=0.f;

    int arow=lane&15,  acol=(lane>>4)*8;
    int brow=lane&7,   bcol=((lane>>3)&1)*8;
    int lrow=tid>>1, lcb=(tid&1)*16;
    int pr=m0+lrow; if(pr>=P) pr=P-1;

    for(int c=0;c<8;c++){
        int k0=c*32;
        {
            int sb=lrow*SSTR+lcb;
            const __nv_bfloat16* sh=&Yhb[(long)pr*256+k0+lcb];
            const __nv_bfloat16* sl=&Ylb[(long)pr*256+k0+lcb];
            *(uint4*)&sAh[sb]  =*(const uint4*)&sh[0];
            *(uint4*)&sAh[sb+8]=*(const uint4*)&sh[8];
            *(uint4*)&sAl[sb]  =*(const uint4*)&sl[0];
            *(uint4*)&sAl[sb+8]=*(const uint4*)&sl[8];
        }
        {
            int co=n0+lrow;
            const float* ps=&pw[(long)co*256+k0+lcb];
            const float* ss=&svp[k0+lcb];
            __nv_bfloat16 h[16], l[16];
            #pragma unroll
            for(int g=0;g<4;g++){
                float4 v=*(const float4*)&ps[g*4];
                float4 s4=*(const float4*)&ss[g*4];
                float vv[4]={v.x*s4.x,v.y*s4.y,v.z*s4.z,v.w*s4.w};
                #pragma unroll
                for(int u=0;u<4;u++){
                    __nv_bfloat16 hh=__float2bfloat16(vv[u]);
                    h[g*4+u]=hh;
                    l[g*4+u]=__float2bfloat16(vv[u]-__bfloat162float(hh));
                }
            }
            int sb=lrow*SSTR+lcb;
            *(uint4*)&sBh[sb]  =*(const uint4*)&h[0];
            *(uint4*)&sBh[sb+8]=*(const uint4*)&h[8];
            *(uint4*)&sBl[sb]  =*(const uint4*)&l[0];
            *(uint4*)&sBl[sb+8]=*(const uint4*)&l[8];
        }
        __syncthreads();
        #pragma unroll
        for(int ks=0;ks<2;ks++){
            int kk=ks*16;
            uint32_t bh[4][2], bl[4][2];
            #pragma unroll
            for(int nt=0;nt<4;nt++){
                uint32_t boff=(uint32_t)((wn*32+nt*8+brow)*SSTR + kk+bcol)*2u;
                ldsm2(bh[nt], bBh+boff);
                ldsm2(bl[nt], bBl+boff);
            }
            #pragma unroll
            for(int mt=0;mt<4;mt++){
                uint32_t aoff=(uint32_t)((wm*64+mt*16+arow)*SSTR + kk+acol)*2u;
                uint32_t ah[4], al[4];
                ldsm4(ah, bAh+aoff);
                ldsm4(al, bAl+aoff);
                #pragma unroll
                for(int nt=0;nt<4;nt++){
                    mma16816(acc[mt][nt], ah, bh[nt]);
                    mma16816(acc[mt][nt], al, bh[nt]);
                    mma16816(acc[mt][nt], ah, bl[nt]);
                }
            }
        }
        __syncthreads();
    }

    int rl=lane>>2, cl=(lane&3)*2;
    #pragma unroll
    for(int mt=0;mt<4;mt++){
        int r0=wm*64+mt*16+rl, r1=r0+8;
        #pragma unroll
        for(int nt=0;nt<4;nt++){
            int nl=wn*32+nt*8+cl;
            float* d=acc[mt][nt];
            if(m0+r0<P) *(float2*)&zb[(long)(m0+r0)*256 + n0+nl]=make_float2(d[0],d[1]);
            if(m0+r1<P) *(float2*)&zb[(long)(m0+r1)*256 + n0+nl]=make_float2(d[2],d[3]);
        }
    }
}

// ---------------- NHWC residual + maxpool ----------------
__global__ void k_respool_nhwc(const float* __restrict__ xin, const float* __restrict__ z,
        float* __restrict__ out, int Hin, int Hout, int windowed){
    int gid=blockIdx.x*256+threadIdx.x;
    int cq=gid&63; int t=gid>>6;
    int wo=t%Hout; t/=Hout;
    int ho=t%Hout; int n=t/Hout;
    if(n>=NB) return;
    int c=cq*4;
    float4 mx=make_float4(-INFINITY,-INFINITY,-INFINITY,-INFINITY);
    #pragma unroll
    for(int kh=0;kh<3;kh++){
        int hh=2*ho-1+kh;
        if(hh<0||hh>=Hin) continue;
        #pragma unroll
        for(int kw=0;kw<3;kw++){
            int ww=2*wo-1+kw;
            if(ww<0||ww>=Hin) continue;
            long zoff=((long)n*Hin*Hin + hh*Hin+ww)*256 + c;
            float4 a=*(const float4*)&z[zoff];
            long xoff = windowed ? pix_off(n,hh,ww)+c : zoff;
            float4 b=*(const float4*)&xin[xoff];
            mx.x=fmaxf(mx.x,a.x+b.x); mx.y=fmaxf(mx.y,a.y+b.y);
            mx.z=fmaxf(mx.z,a.z+b.z); mx.w=fmaxf(mx.w,a.w+b.w);
        }
    }
    *(float4*)&out[((long)n*Hout*Hout + ho*Hout+wo)*256 + c]=mx;
}

// ---------------- HMMA GEMM (QKV only, mode-0 path) ----------------
__global__ void __launch_bounds__(256) k_mmagemm(const float* __restrict__ Axf,
        const __nv_bfloat16* __restrict__ Wh, const __nv_bfloat16* __restrict__ Wl,
        const float* __restrict__ bias){
    __shared__ __align__(16) __nv_bfloat16 sAh[128*SSTR];
    __shared__ __align__(16) __nv_bfloat16 sAl[128*SSTR];
    __shared__ __align__(16) __nv_bfloat16 sBh[128*SSTR];
    __shared__ __align__(16) __nv_bfloat16 sBl[128*SSTR];
    __shared__ long roff[128];
    __shared__ float bsh[128];

    int tid=threadIdx.x;
    int wid=tid>>5, lane=tid&31;
    int wm=wid&1, wn=wid>>1;
    int m0=blockIdx.y*128, n0=blockIdx.x*128;

    if(tid<128){
        roff[tid]=xrow_off(m0+tid);
        bsh[tid]=bias[n0+tid];
    }
    __syncthreads();

    uint32_t bAh=smem_u32(sAh), bAl=smem_u32(sAl);
    uint32_t bBh=smem_u32(sBh), bBl=smem_u32(sBl);

    float acc[4][4][4];
    #pragma unroll
    for(int i=0;i<4;i++)
        #pragma unroll
        for(int j=0;j<4;j++)
            #pragma unroll
            for(int e=0;e<4;e++) acc[i][j][e]=0.f;

    int arow=lane&15,  acol=(lane>>4)*8;
    int brow=lane&7,   bcol=((lane>>3)&1)*8;
    int lrow=tid>>1, lcb=(tid&1)*16;

    for(int c=0;c<8;c++){
        int k0=c*32;
        {
            const float* src=&Axf[roff[lrow]+k0+lcb];
            __nv_bfloat16 h[16], l[16];
            #pragma unroll
            for(int g=0;g<4;g++){
                float4 v=*(const float4*)&src[g*4];
                float vv[4]={v.x,v.y,v.z,v.w};
                #pragma unroll
                for(int u=0;u<4;u++){
                    __nv_bfloat16 hh=__float2bfloat16(vv[u]);
                    h[g*4+u]=hh;
                    l[g*4+u]=__float2bfloat16(vv[u]-__bfloat162float(hh));
                }
            }
            int sb=lrow*SSTR+lcb;
            *(uint4*)&sAh[sb]  =*(const uint4*)&h[0];
            *(uint4*)&sAh[sb+8]=*(const uint4*)&h[8];
            *(uint4*)&sAl[sb]  =*(const uint4*)&l[0];
            *(uint4*)&sAl[sb+8]=*(const uint4*)&l[8];
        }
        {
            const __nv_bfloat16* sh=&Wh[(long)(n0+lrow)*256+k0+lcb];
            const __nv_bfloat16* sl=&Wl[(long)(n0+lrow)*256+k0+lcb];
            int sb=lrow*SSTR+lcb;
            *(uint4*)&sBh[sb]  =*(const uint4*)&sh[0];
            *(uint4*)&sBh[sb+8]=*(const uint4*)&sh[8];
            *(uint4*)&sBl[sb]  =*(const uint4*)&sl[0];
            *(uint4*)&sBl[sb+8]=*(const uint4*)&sl[8];
        }
        __syncthreads();
        #pragma unroll
        for(int ks=0;ks<2;ks++){
            int kk=ks*16;
            uint32_t bh[4][2], bl[4][2];
            #pragma unroll
            for(int nt=0;nt<4;nt++){
                uint32_t boff=(uint32_t)((wn*32+nt*8+brow)*SSTR + kk+bcol)*2u;
                ldsm2(bh[nt], bBh+boff);
                ldsm2(bl[nt], bBl+boff);
            }
            #pragma unroll
            for(int mt=0;mt<4;mt++){
                uint32_t aoff=(uint32_t)((wm*64+mt*16+arow)*SSTR + kk+acol)*2u;
                uint32_t ah[4], al[4];
                ldsm4(ah, bAh+aoff);
                ldsm4(al, bAl+aoff);
                #pragma unroll
                for(int nt=0;nt<4;nt++){
                    mma16816(acc[mt][nt], ah, bh[nt]);
                    mma16816(acc[mt][nt], al, bh[nt]);
                    mma16816(acc[mt][nt], ah, bl[nt]);
                }
            }
        }
        __syncthreads();
    }

    int rl=lane>>2, cl=(lane&3)*2;
    #pragma unroll
    for(int mt=0;mt<4;mt++){
        int r0=wm*64+mt*16+rl, r1=r0+8;
        #pragma unroll
        for(int nt=0;nt<4;nt++){
            int nl=wn*32+nt*8+cl;
            float* d=acc[mt][nt];
            float b0=bsh[nl], b1=bsh[nl+1];
            float* p0=&g_kv[(long)(m0+r0)*512 + n0+nl];
            float* p1=&g_kv[(long)(m0+r1)*512 + n0+nl];
            p0[0]=d[0]+b0; p0[1]=d[1]+b1;
            p1[0]=d[2]+b0; p1[1]=d[3]+b1;
        }
    }
}

// ---------------- to_out GEMM: cp.async double-buffered, all-bf16 operands ----------------
// dynamic smem: 2 buffers x 4 arrays x 128*SSTR halves = 81920 B
__global__ void __launch_bounds__(256) k_toout(const __nv_bfloat16* __restrict__ Ah_,
        const __nv_bfloat16* __restrict__ Al_,
        const __nv_bfloat16* __restrict__ Wh, const __nv_bfloat16* __restrict__ Wl,
        float* __restrict__ Cb){
    __shared__ long roff[128];
    __nv_bfloat16* sbuf=(__nv_bfloat16*)dsm;
    uint32_t base=smem_u32(sbuf);
    int tid=threadIdx.x;
    int wid=tid>>5, lane=tid&31;
    int wm=wid&1, wn=wid>>1;
    int m0=blockIdx.y*128, n0=blockIdx.x*128;
    if(tid<128) roff[tid]=xrow_off(m0+tid);

    int lrow=tid>>1, lcb=(tid&1)*16;
    const long abase=(long)(m0+lrow)*256 + lcb;
    const long bbase=(long)(n0+lrow)*256 + lcb;
    const uint32_t dd=base + (uint32_t)(lrow*80 + lcb*2);

    float acc[4][4][4];
    #pragma unroll
    for(int i=0;i<4;i++)
        #pragma unroll
        for(int j=0;j<4;j++)
            #pragma unroll
            for(int e=0;e<4;e++) acc[i][j][e]=0.f;

    int arow=lane&15, acol=(lane>>4)*8;
    int brow=lane&7,  bcol=((lane>>3)&1)*8;

    // issue chunk 0 into buffer 0
    {
        cpa16(dd,          &Ah_[abase]);  cpa16(dd+16,          &Ah_[abase+8]);
        cpa16(dd+10240,    &Al_[abase]);  cpa16(dd+10240+16,    &Al_[abase+8]);
        cpa16(dd+20480,    &Wh[bbase]);   cpa16(dd+20480+16,    &Wh[bbase+8]);
        cpa16(dd+30720,    &Wl[bbase]);   cpa16(dd+30720+16,    &Wl[bbase+8]);
        CPCOMMIT();
    }

    for(int c=0;c<8;c++){
        int cur=c&1;
        CPWAIT0();
        __syncthreads();
        if(c<7){
            uint32_t d2=dd + (uint32_t)((cur^1)*40960);
            long ao=abase+(long)(c+1)*32, bo=bbase+(long)(c+1)*32;
            cpa16(d2,          &Ah_[ao]);  cpa16(d2+16,          &Ah_[ao+8]);
            cpa16(d2+10240,    &Al_[ao]);  cpa16(d2+10240+16,    &Al_[ao+8]);
            cpa16(d2+20480,    &Wh[bo]);   cpa16(d2+20480+16,    &Wh[bo+8]);
            cpa16(d2+30720,    &Wl[bo]);   cpa16(d2+30720+16,    &Wl[bo+8]);
            CPCOMMIT();
        }
        uint32_t cb=base + (uint32_t)(cur*40960);
        #pragma unroll
        for(int ks=0;ks<2;ks++){
            int kk=ks*16;
            uint32_t bh[4][2], bl[4][2];
            #pragma unroll
            for(int nt=0;nt<4;nt++){
                uint32_t boff=(uint32_t)((wn*32+nt*8+brow)*SSTR + kk+bcol)*2u;
                ldsm2(bh[nt], cb+20480u+boff);
                ldsm2(bl[nt], cb+30720u+boff);
            }
            #pragma unroll
            for(int mt=0;mt<4;mt++){
                uint32_t aoff=(uint32_t)((wm*64+mt*16+arow)*SSTR + kk+acol)*2u;
                uint32_t ah[4], al[4];
                ldsm4(ah, cb+aoff);
                ldsm4(al, cb+10240u+aoff);
                #pragma unroll
                for(int nt=0;nt<4;nt++){
                    mma16816(acc[mt][nt], ah, bh[nt]);
                    mma16816(acc[mt][nt], al, bh[nt]);
                    mma16816(acc[mt][nt], ah, bl[nt]);
                }
            }
        }
    }

    int rl=lane>>2, cl=(lane&3)*2;
    #pragma unroll
    for(int mt=0;mt<4;mt++){
        int r0=wm*64+mt*16+rl, r1=r0+8;
        #pragma unroll
        for(int nt=0;nt<4;nt++){
            int nl=wn*32+nt*8+cl;
            float* d=acc[mt][nt];
            float* p0=&Cb[roff[r0] + n0+nl];
            float* p1=&Cb[roff[r1] + n0+nl];
            p0[0]=d[0]; p0[1]=d[1];
            p1[0]=d[2]; p1[1]=d[3];
        }
    }
}

// ---------------- HMMA window attention (register-resident P) ----------------
#define QSTR 40
#define PSTR 120
#define OQH 0
#define OQL (OQH+112*QSTR)
#define OKH (OQL+112*QSTR)
#define OKL (OKH+112*QSTR)
#define OVH (OKL+112*QSTR)
#define OVL (OVH+32*PSTR)
#define WSM_HALVES (OVL+32*PSTR)
__global__ void __launch_bounds__(256,2) k_wattn(){
    __nv_bfloat16* sb=(__nv_bfloat16*)dsm;
    int wh=blockIdx.x; int head=wh&7; int win=wh>>3; int b=win>>6;
    int tid=threadIdx.x, wid=tid>>5, lane=tid&31;
    const float scale=0.17677669529663687f;

    for(int e=tid;e<WSM_HALVES/8;e+=256) ((uint4*)sb)[e]=make_uint4(0,0,0,0);
    __syncthreads();

    for(int e=tid;e<224;e+=256){
        int row=e>>1, half=(e&1)*16;
        if(row<98){
            const float* qs=&g_qglob[((long)b*98+row)*256 + head*32 + half];
            const float* ks=&g_kv[(((long)win*98+row))*512 + head*32 + half];
            uint32_t qh[8], ql[8], kh[8], kl[8];
            #pragma unroll
            for(int u=0;u<8;u++){
                float q0=qs[2*u]*scale, q1=qs[2*u+1]*scale;
                qh[u]=bsplit2(q0,q1,ql[u]);
                kh[u]=bsplit2(ks[2*u],ks[2*u+1],kl[u]);
            }
            int sbo=row*QSTR+half;
            *(uint4*)&sb[OQH+sbo]  =*(uint4*)&qh[0];
            *(uint4*)&sb[OQH+sbo+8]=*(uint4*)&qh[4];
            *(uint4*)&sb[OQL+sbo]  =*(uint4*)&ql[0];
            *(uint4*)&sb[OQL+sbo+8]=*(uint4*)&ql[4];
            *(uint4*)&sb[OKH+sbo]  =*(uint4*)&kh[0];
            *(uint4*)&sb[OKH+sbo+8]=*(uint4*)&kh[4];
            *(uint4*)&sb[OKL+sbo]  =*(uint4*)&kl[0];
            *(uint4*)&sb[OKL+sbo+8]=*(uint4*)&kl[4];
        }
    }
    for(int e=tid;e<196;e+=256){
        int row=e>>1, half=(e&1)*16;
        const float* vs=&g_kv[(((long)win*98+row))*512 + 256 + head*32 + half];
        #pragma unroll
        for(int u=0;u<16;u++){
            float vv=vs[u];
            __nv_bfloat16 h=__float2bfloat16(vv);
            __nv_bfloat16 l=__float2bfloat16(vv-__bfloat162float(h));
            int c=half+u;
            sb[OVH+c*PSTR+row]=h;
            sb[OVL+c*PSTR+row]=l;
        }
    }
    __syncthreads();

    uint32_t base=smem_u32(sb);
    int arow=lane&15, acol=(lane>>4)*8;
    int brow=lane&7,  bcol=((lane>>3)&1)*8;
    int rl=lane>>2, cl=(lane&3)*2;

    if(wid<7){
        float sacc[13][4];
        #pragma unroll
        for(int nt=0;nt<13;nt++){
            #pragma unroll
            for(int e2=0;e2<4;e2++) sacc[nt][e2]=0.f;
        }
        #pragma unroll
        for(int kc=0;kc<2;kc++){
            int kk=kc*16;
            uint32_t aoff=(uint32_t)((wid*16+arow)*QSTR + kk+acol)*2u;
            uint32_t ah[4], al[4];
            ldsm4(ah, base+(OQH*2u)+aoff);
            ldsm4(al, base+(OQL*2u)+aoff);
            #pragma unroll
            for(int nt=0;nt<13;nt++){
                uint32_t boff=(uint32_t)((nt*8+brow)*QSTR + kk+bcol)*2u;
                uint32_t bh[2], bl[2];
                ldsm2(bh, base+(OKH*2u)+boff);
                ldsm2(bl, base+(OKL*2u)+boff);
                mma16816(sacc[nt], ah, bh);
                mma16816(sacc[nt], al, bh);
                mma16816(sacc[nt], ah, bl);
            }
        }
        int r0=wid*16+rl, r1=r0+8;
        const float* bbase=&g_biasb[(long)head*9604];
        #pragma unroll
        for(int nt=0;nt<13;nt++){
            int j0=nt*8+cl;
            if(j0>=98){
                sacc[nt][0]=-1e30f; sacc[nt][1]=-1e30f;
                sacc[nt][2]=-1e30f; sacc[nt][3]=-1e30f;
            }else{
                if(r0<98){
                    float2 bb=*(const float2*)&bbase[r0*98+j0];
                    sacc[nt][0]+=bb.x; sacc[nt][1]+=bb.y;
                }
                if(r1<98){
                    float2 bb=*(const float2*)&bbase[r1*98+j0];
                    sacc[nt][2]+=bb.x; sacc[nt][3]+=bb.y;
                }
            }
        }
        float mx0=-1e30f, mx1=-1e30f;
        #pragma unroll
        for(int nt=0;nt<13;nt++){
            mx0=fmaxf(mx0,fmaxf(sacc[nt][0],sacc[nt][1]));
            mx1=fmaxf(mx1,fmaxf(sacc[nt][2],sacc[nt][3]));
        }
        mx0=fmaxf(mx0,__shfl_xor_sync(~0u,mx0,1)); mx0=fmaxf(mx0,__shfl_xor_sync(~0u,mx0,2));
        mx1=fmaxf(mx1,__shfl_xor_sync(~0u,mx1,1)); mx1=fmaxf(mx1,__shfl_xor_sync(~0u,mx1,2));
        float sum0=0.f, sum1=0.f;
        #pragma unroll
        for(int nt=0;nt<13;nt++){
            sacc[nt][0]=__expf(sacc[nt][0]-mx0); sum0+=sacc[nt][0];
            sacc[nt][1]=__expf(sacc[nt][1]-mx0); sum0+=sacc[nt][1];
            sacc[nt][2]=__expf(sacc[nt][2]-mx1); sum1+=sacc[nt][2];
            sacc[nt][3]=__expf(sacc[nt][3]-mx1); sum1+=sacc[nt][3];
        }
        sum0+=__shfl_xor_sync(~0u,sum0,1); sum0+=__shfl_xor_sync(~0u,sum0,2);
        sum1+=__shfl_xor_sync(~0u,sum1,1); sum1+=__shfl_xor_sync(~0u,sum1,2);
        float inv0=1.f/sum0, inv1=1.f/sum1;

        uint32_t phi[7][4], plo[7][4];
        #pragma unroll
        for(int t7=0;t7<7;t7++){
            int nt0=2*t7, nt1=2*t7+1;
            phi[t7][0]=bsplit2(sacc[nt0][0]*inv0, sacc[nt0][1]*inv0, plo[t7][0]);
            phi[t7][1]=bsplit2(sacc[nt0][2]*inv1, sacc[nt0][3]*inv1, plo[t7][1]);
            if(nt1<13){
                phi[t7][2]=bsplit2(sacc[nt1][0]*inv0, sacc[nt1][1]*inv0, plo[t7][2]);
                phi[t7][3]=bsplit2(sacc[nt1][2]*inv1, sacc[nt1][3]*inv1, plo[t7][3]);
            }else{
                phi[t7][2]=0u; plo[t7][2]=0u;
                phi[t7][3]=0u; plo[t7][3]=0u;
            }
        }

        float oacc[4][4];
        #pragma unroll
        for(int nt=0;nt<4;nt++)
            #pragma unroll
            for(int e2=0;e2<4;e2++) oacc[nt][e2]=0.f;
        #pragma unroll
        for(int t7=0;t7<7;t7++){
            int kk=t7*16;
            #pragma unroll
            for(int nt=0;nt<4;nt++){
                uint32_t boff=(uint32_t)((nt*8+brow)*PSTR + kk+bcol)*2u;
                uint32_t bh[2], bl[2];
                ldsm2(bh, base+(OVH*2u)+boff);
                ldsm2(bl, base+(OVL*2u)+boff);
                mma16816(oacc[nt], phi[t7], bh);
                mma16816(oacc[nt], plo[t7], bh);
                mma16816(oacc[nt], phi[t7], bl);
            }
        }
        #pragma unroll
        for(int nt=0;nt<4;nt++){
            int c=nt*8+cl;
            uint32_t lo0, lo1;
            uint32_t hi0=bsplit2(oacc[nt][0], oacc[nt][1], lo0);
            uint32_t hi1=bsplit2(oacc[nt][2], oacc[nt][3], lo1);
            if(r0<98){
                long bse=((long)win*98+r0)*256 + head*32 + c;
                *(uint32_t*)&g_aouth[bse]=hi0;
                *(uint32_t*)&g_aoutl[bse]=lo0;
            }
            if(r1<98){
                long bse=((long)win*98+r1)*256 + head*32 + c;
                *(uint32_t*)&g_aouth[bse]=hi1;
                *(uint32_t*)&g_aoutl[bse]=lo1;
            }
        }
    }
}

// ---------------- gattn stage 1 ----------------
__global__ void k_gattn1(){
    float* X=dsm;
    float* S=dsm+98*260;
    int bg=blockIdx.x, chunk=blockIdx.y;
    int b=bg>>2, g=bg&3, nx=g>>1, ny=g&1;
    int tid=threadIdx.x;
    for(int e=tid;e<98*256;e+=256){
        int c=e&255, i=e>>8;
        int m=i/49, rr=i%49, w1=rr/7, w2=rr%7;
        int n=b*2+m;
        int pix=(nx*7+w1)*14 + ny*7+w2;
        X[i*260+c]=g_xg2[((long)n*196+pix)*256 + c];
    }
    __syncthreads();
    int i0=chunk*26;
    int ni=min(26,98-i0);
    int npair=ni>>1;
    for(int t=tid;t<13*49;t+=256){
        int ip=t/49, jp=t%49;
        if(ip>=npair) continue;
        int i=i0+ip*2, j=jp*2;
        const ull* xi0=(const ull*)&X[i*260];
        const ull* xi1=(const ull*)&X[(i+1)*260];
        const ull* xj0=(const ull*)&X[j*260];
        const ull* xj1=(const ull*)&X[(j+1)*260];
        ull a00=0,a01=0,a10=0,a11=0;
        #pragma unroll 8
        for(int cp=0;cp<128;cp++){
            ull q0=xi0[cp],q1=xi1[cp],p0=xj0[cp],p1=xj1[cp];
            fma2(a00,q0,p0); fma2(a01,q0,p1); fma2(a10,q1,p0); fma2(a11,q1,p1);
        }
        float2 t00=upk(a00),t01=upk(a01),t10=upk(a10),t11=upk(a11);
        int il=i-i0;
        S[il*100+j]      =t00.x+t00.y;
        S[il*100+j+1]    =t01.x+t01.y;
        S[(il+1)*100+j]  =t10.x+t10.y;
        S[(il+1)*100+j+1]=t11.x+t11.y;
    }
    __syncthreads();
    int wd=tid>>5, lane=tid&31;
    for(int r=wd;r<ni;r+=8){
        float mx=-INFINITY;
        for(int j=lane;j<98;j+=32) mx=fmaxf(mx,S[r*100+j]);
        for(int o=16;o>0;o>>=1) mx=fmaxf(mx,__shfl_xor_sync(~0u,mx,o));
        float sum=0.f;
        for(int j=lane;j<98;j+=32){ float e=__expf(S[r*100+j]-mx); S[r*100+j]=e; sum+=e; }
        for(int o=16;o>0;o>>=1) sum+=__shfl_xor_sync(~0u,sum,o);
        float inv=0.0625f/sum;
        float* gs=&g_S[((long)bg*98 + i0+r)*98];
        for(int j=lane;j<98;j+=32) gs[j]=S[r*100+j]*inv;
    }
}

// ---------------- gattn stage 2 ----------------
__global__ void k_gattn2(){
    float* X=dsm;
    float* Ssh=dsm+98*260;
    int bg=blockIdx.x, chunk=blockIdx.y;
    int b=bg>>2, g=bg&3, nx=g>>1, ny=g&1;
    int tid=threadIdx.x;
    for(int e=tid;e<98*256;e+=256){
        int c=e&255, i=e>>8;
        int m=i/49, rr=i%49, w1=rr/7, w2=rr%7;
        int n=b*2+m;
        int pix=(nx*7+w1)*14 + ny*7+w2;
        X[i*260+c]=g_xg2[((long)n*196+pix)*256 + c];
    }
    int i0=chunk*26;
    int ni=min(26,98-i0);
    for(int e=tid;e<ni*98;e+=256){
        int r=e/98, j=e%98;
        Ssh[r*100+j]=g_S[((long)bg*98 + i0+r)*98 + j];
    }
    __syncthreads();
    int npair=ni>>1;
    for(int t=tid;t<13*64;t+=256){
        int ip=t>>6, cq=t&63;
        if(ip>=npair) continue;
        int i=i0+2*ip, c=cq*4;
        ull a00=0,a01=0,a10=0,a11=0;
        const float* S0=&Ssh[(2*ip)*100];
        const float* S1=&Ssh[(2*ip+1)*100];
        for(int j=0;j<98;j++){
            ull s0=pk2(S0[j]), s1=pk2(S1[j]);
            const ull* vp=(const ull*)&X[j*260+c];
            ull v0=vp[0], v1=vp[1];
            fma2(a00,s0,v0); fma2(a01,s0,v1);
            fma2(a10,s1,v0); fma2(a11,s1,v1);
        }
        float2 x00=upk(a00),x01=upk(a01),x10=upk(a10),x11=upk(a11);
        long basep=((long)bg*98+i)*256+c;
        *(float4*)&g_gout[basep]    =make_float4(x00.x,x00.y,x01.x,x01.y);
        *(float4*)&g_gout[basep+256]=make_float4(x10.x,x10.y,x11.x,x11.y);
    }
}

// ---------------- mean over 4 groups ----------------
__global__ void k_qmean(){
    int o=blockIdx.x*blockDim.x+threadIdx.x;
    if(o>=8*NTOK*D) return;
    int c=o&255; int t=o>>8; int i=t%NTOK; int b=t/NTOK;
    float a=0.f;
    for(int g=0;g<4;g++) a+=g_gout[(((long)(b*4+g)*NTOK)+i)*D+c];
    g_qglob[o]=a*0.25f;
}

// ---------------- RPE bias gather ----------------
__global__ void k_bias(const float* __restrict__ rpe){
    int o=blockIdx.x*blockDim.x+threadIdx.x;
    if(o>=NH*NTOK*NTOK) return;
    int j=o%NTOK; int t=o/NTOK; int i=t%NTOK; int h=t/NTOK;
    int mi=i/49, ri=i%49, ai=ri/7, bi=ri%7;
    int mj=j/49, rj=j%49, aj=rj/7, bj=rj%7;
    int idx=(mi-mj+1)*169 + (ai-aj+6)*13 + (bi-bj+6);
    g_biasb[o]=rpe[idx*NH+h];
}

// ---------------- side stream/events ----------------
struct SideStream {
    cudaStream_t s;
    cudaEvent_t eFork, eJoin;
    SideStream(){
        cudaStreamCreateWithFlags(&s, cudaStreamNonBlocking);
        cudaEventCreateWithFlags(&eFork, cudaEventDisableTiming);
        cudaEventCreateWithFlags(&eJoin, cudaEventDisableTiming);
    }
};
static SideStream g_ss;

// ---------------- host ----------------
extern "C" void kernel_launch(void* const* d_in, const int* in_sizes, int n_in,
                              void* d_out, int out_size){
    (void)in_sizes; (void)n_in; (void)out_size;
    const float* x       =(const float*)d_in[0];
    const float* qkv_w   =(const float*)d_in[1];
    const float* qkv_b   =(const float*)d_in[2];
    const float* to_out_w=(const float*)d_in[3];
    const float* rpe     =(const float*)d_in[4];
    const float* fe1_dw  =(const float*)d_in[5];
    const float* fe1_se1 =(const float*)d_in[6];
    const float* fe1_se2 =(const float*)d_in[7];
    const float* fe1_pw  =(const float*)d_in[8];
    const float* fe2_dw  =(const float*)d_in[9];
    const float* fe2_se1 =(const float*)d_in[10];
    const float* fe2_se2 =(const float*)d_in[11];
    const float* fe2_pw  =(const float*)d_in[12];
    float* outp=(float*)d_out;

    float *zb,*xg1,*xg2,*svec;
    __nv_bfloat16 *yh,*yl,*wqh,*wql,*woh,*wol,*aoh,*aol;
    cudaGetSymbolAddress((void**)&yh,   g_Yh);
    cudaGetSymbolAddress((void**)&yl,   g_Yl);
    cudaGetSymbolAddress((void**)&zb,   g_z);
    cudaGetSymbolAddress((void**)&xg1,  g_xg1);
    cudaGetSymbolAddress((void**)&xg2,  g_xg2);
    cudaGetSymbolAddress((void**)&svec, g_svec);
    cudaGetSymbolAddress((void**)&wqh,  g_Wqh);
    cudaGetSymbolAddress((void**)&wql,  g_Wql);
    cudaGetSymbolAddress((void**)&woh,  g_Woh);
    cudaGetSymbolAddress((void**)&wol,  g_Wol);
    cudaGetSymbolAddress((void**)&aoh,  g_aouth);
    cudaGetSymbolAddress((void**)&aol,  g_aoutl);

    const int GATTN_SMEM=(98*260 + 26*100)*4;
    const int WATTN_SMEM=WSM_HALVES*2;
    const int TOOUT_SMEM=81920;
    cudaFuncSetAttribute(k_gattn1, cudaFuncAttributeMaxDynamicSharedMemorySize, GATTN_SMEM);
    cudaFuncSetAttribute(k_gattn2, cudaFuncAttributeMaxDynamicSharedMemorySize, GATTN_SMEM);
    cudaFuncSetAttribute(k_wattn,  cudaFuncAttributeMaxDynamicSharedMemorySize, WATTN_SMEM);
    cudaFuncSetAttribute(k_toout,  cudaFuncAttributeMaxDynamicSharedMemorySize, TOOUT_SMEM);

    // ---- fork: independent QKV/weight/bias chain on side stream ----
    cudaEventRecord(g_ss.eFork, 0);
    cudaStreamWaitEvent(g_ss.s, g_ss.eFork, 0);
    k_prep_w<<<(512*256+255)/256,256,0,g_ss.s>>>(qkv_w, wqh, wql, 512);
    k_prep_w<<<(256*256+255)/256,256,0,g_ss.s>>>(to_out_w, woh, wol, 256);
    k_mmagemm<<<dim3(4,MROWS/128),256,0,g_ss.s>>>(x, wqh, wql, qkv_b);
    k_bias<<<(NH*NTOK*NTOK+255)/256,256,0,g_ss.s>>>(rpe);
    cudaEventRecord(g_ss.eJoin, g_ss.s);

    // ---- main chain: conv pyramid + global attention ----
    k_dwconv_nhwc<<<NB*H1*(H1/4)*64/256,256>>>(x, fe1_dw, yh, yl, H1, 1);
    k_semean<<<NB*64,256>>>(yh, yl, H1*H1, 64);
    k_se2<<<NB,256>>>(fe1_se1, fe1_se2, svec, H1*H1, 64);
    k_pwmma<<<dim3(2,25,NB),256>>>(yh, yl, fe1_pw, svec, zb, H1*H1);
    k_respool_nhwc<<<NB*H2*H2*64/256,256>>>(x, zb, xg1, H1, H2, 1);
    k_dwconv_nhwc<<<NB*H2*(H2/4)*64/256,256>>>(xg1, fe2_dw, yh, yl, H2, 0);
    k_semean<<<NB*16,256>>>(yh, yl, H2*H2, 16);
    k_se2<<<NB,256>>>(fe2_se1, fe2_se2, svec, H2*H2, 16);
    k_pwmma<<<dim3(2,7,NB),256>>>(yh, yl, fe2_pw, svec, zb, H2*H2);
    k_respool_nhwc<<<NB*H3*H3*64/256,256>>>(xg1, zb, xg2, H2, H3, 0);
    k_gattn1<<<dim3(32,4),256,GATTN_SMEM>>>();
    k_gattn2<<<dim3(32,4),256,GATTN_SMEM>>>();
    k_qmean<<<(8*NTOK*D+255)/256,256>>>();

    // ---- join, then window attention + output projection ----
    cudaStreamWaitEvent(0, g_ss.eJoin, 0);
    k_wattn<<<NWIN*NH,256,WATTN_SMEM>>>();
    k_toout<<<dim3(2,MROWS/128),256,TOOUT_SMEM>>>(aoh, aol, woh, wol, outp);
}